// round 2
// baseline (speedup 1.0000x reference)
#include <cuda_runtime.h>
#include <cuda_bf16.h>
#include <math.h>

// Problem constants
#define BSZ   2
#define SEQ   2048
#define DM    2048
#define NH    16
#define NKV   8
#define HD    128
#define DQK   256   // concatenated (real,imag) encoding dim

// ---------------------------------------------------------------------------
// Scratch (static __device__ arrays; no allocation allowed)
// ---------------------------------------------------------------------------
__device__ float g_q [BSZ * SEQ * NH  * HD];   //  (B*T, 2048)
__device__ float g_k [BSZ * SEQ * NKV * HD];   //  (B*T, 1024)
__device__ float g_v [BSZ * SEQ * NKV * HD];   //  (B*T, 1024)
__device__ float g_qe[(size_t)BSZ * NH  * SEQ * DQK]; // (B,16,T,256)
__device__ float g_ke[(size_t)BSZ * NH  * SEQ * DQK]; // (B,16,T,256)
__device__ float g_vt[(size_t)BSZ * NKV * SEQ * HD];  // (B,8,T,128)
__device__ float g_y [BSZ * SEQ * NH  * HD];   //  (B*T, 2048)

// ---------------------------------------------------------------------------
// SGEMM: C[M,N] = A[M,K] * B[K,N], row-major, M%128==0, N%128==0, K%8==0
// 128x128 block tile, BK=8, 256 threads, 8x8 microtile.
// ---------------------------------------------------------------------------
__global__ void __launch_bounds__(256)
sgemm_kernel(const float* __restrict__ A, const float* __restrict__ B,
             float* __restrict__ C, int M, int N, int K)
{
    __shared__ float As[8][128];   // transposed A tile: As[k][m]
    __shared__ float Bs[8][128];

    const int bx = blockIdx.x;             // N tile
    const int by = blockIdx.y;             // M tile
    const int tid = threadIdx.x;
    const int tx = tid & 15;
    const int ty = tid >> 4;

    const float* Ab = A + (size_t)by * 128 * K;
    const float* Bb = B + (size_t)bx * 128;

    const int arow = tid >> 1;             // 0..127
    const int acol = (tid & 1) * 4;        // 0 or 4
    const int brow = tid >> 5;             // 0..7
    const int bcol = (tid & 31) * 4;       // 0..124

    float acc[8][8];
    #pragma unroll
    for (int i = 0; i < 8; i++)
        #pragma unroll
        for (int j = 0; j < 8; j++) acc[i][j] = 0.0f;

    for (int k0 = 0; k0 < K; k0 += 8) {
        float4 av = *(const float4*)(Ab + (size_t)arow * K + k0 + acol);
        float4 bv = *(const float4*)(Bb + (size_t)(k0 + brow) * N + bcol);
        __syncthreads();
        As[acol + 0][arow] = av.x;
        As[acol + 1][arow] = av.y;
        As[acol + 2][arow] = av.z;
        As[acol + 3][arow] = av.w;
        *(float4*)(&Bs[brow][bcol]) = bv;
        __syncthreads();
        #pragma unroll
        for (int kk = 0; kk < 8; kk++) {
            float a[8], b[8];
            *(float4*)(a)     = *(const float4*)(&As[kk][ty * 8]);
            *(float4*)(a + 4) = *(const float4*)(&As[kk][ty * 8 + 4]);
            *(float4*)(b)     = *(const float4*)(&Bs[kk][tx * 8]);
            *(float4*)(b + 4) = *(const float4*)(&Bs[kk][tx * 8 + 4]);
            #pragma unroll
            for (int i = 0; i < 8; i++)
                #pragma unroll
                for (int j = 0; j < 8; j++)
                    acc[i][j] += a[i] * b[j];
        }
    }

    #pragma unroll
    for (int i = 0; i < 8; i++) {
        size_t row = (size_t)by * 128 + ty * 8 + i;
        float* Cr = C + row * N + (size_t)bx * 128 + tx * 8;
        *(float4*)(Cr)     = *(float4*)(&acc[i][0]);
        *(float4*)(Cr + 4) = *(float4*)(&acc[i][4]);
    }
}

// ---------------------------------------------------------------------------
// Encode: softplus magnitude * (cos,sin) phase, with double-precision
// angle range reduction (robust regardless of fast-math flags).
// One thread per (b,h,t,d), h over all 16 heads.
// ---------------------------------------------------------------------------
__device__ __forceinline__ float softplusf(float x)
{
    if (x > 20.0f)  return x;
    if (x < -20.0f) return expf(x);
    return log1pf(expf(x));
}

__global__ void encode_kernel(const float* __restrict__ q,
                              const float* __restrict__ k,
                              const float* __restrict__ v,
                              const float* __restrict__ delta,
                              float* __restrict__ qe,
                              float* __restrict__ ke,
                              float* __restrict__ vt)
{
    const int i = blockIdx.x * blockDim.x + threadIdx.x;
    const int total = BSZ * NH * SEQ * HD;   // 2^23
    if (i >= total) return;

    const int d = i & (HD - 1);
    const int t = (i >> 7) & (SEQ - 1);
    const int h = (i >> 18) & (NH - 1);
    const int b = i >> 22;

    const double TWO_PI  = 6.283185307179586;
    const double INV_2PI = 0.15915494309189535;

    // freq = exp(-ln(10000) * d / 128)
    const double f   = exp(-9.210340371976184 * (double)d / 128.0);
    const double ang = (double)t * f;

    // ---- Q path ----
    {
        float qv = q[((size_t)(b * SEQ + t)) * (NH * HD) + h * HD + d];
        float mag = softplusf(qv);
        double ar = ang - floor(ang * INV_2PI) * TWO_PI;
        float sa, ca;
        sincosf((float)ar, &sa, &ca);
        size_t o = (((size_t)(b * NH + h)) * SEQ + t) * DQK + d;
        qe[o]      = mag * ca;
        qe[o + HD] = mag * sa;
    }

    // ---- K path (per full head: delta differs per head) ----
    {
        float dl = delta[h * HD + d];
        dl = fminf(fmaxf(dl, -6.2831855f), 0.0f);
        double angk = ang + (double)dl;
        double ar = angk - floor(angk * INV_2PI) * TWO_PI;
        float kv = k[((size_t)(b * SEQ + t)) * (NKV * HD) + (h >> 1) * HD + d];
        float mag = softplusf(kv);
        float sa, ca;
        sincosf((float)ar, &sa, &ca);
        size_t o = (((size_t)(b * NH + h)) * SEQ + t) * DQK + d;
        ke[o]      = mag * ca;
        ke[o + HD] = mag * sa;
    }

    // ---- V transpose (only once per kv head) ----
    if ((h & 1) == 0) {
        vt[(((size_t)(b * NKV + (h >> 1))) * SEQ + t) * HD + d] =
            v[((size_t)(b * SEQ + t)) * (NKV * HD) + (h >> 1) * HD + d];
    }
}

// ---------------------------------------------------------------------------
// Causal flash attention: d_qk = 256, d_v = 128. BM=BN=64, 256 threads.
// Thread (ty,tx): rows r = ty + 16*i (i<4), cols c = tx + 16*j (j<4).
// ---------------------------------------------------------------------------
#define FBM 64
#define FBN 64
#define QK_STRIDE 260
#define V_STRIDE  129
#define P_STRIDE  68

#define FLASH_SMEM_FLOATS (FBM*QK_STRIDE + FBN*QK_STRIDE + FBN*V_STRIDE + FBM*P_STRIDE)

__global__ void __launch_bounds__(256, 1)
flash_kernel(const float* __restrict__ Qe, const float* __restrict__ Ke,
             const float* __restrict__ Vt, float* __restrict__ Y)
{
    extern __shared__ float sm[];
    float* Qs = sm;
    float* Ks = Qs + FBM * QK_STRIDE;
    float* Vs = Ks + FBN * QK_STRIDE;
    float* Ps = Vs + FBN * V_STRIDE;

    const int qt = blockIdx.x;
    const int h  = blockIdx.y;
    const int b  = blockIdx.z;
    const int q0 = qt * FBM;

    const int tid = threadIdx.x;
    const int tx = tid & 15;
    const int ty = tid >> 4;

    const float* qbase = Qe + (((size_t)(b * NH + h)) * SEQ + q0) * DQK;
    const float* kbase = Ke + (((size_t)(b * NH + h)) * SEQ) * DQK;
    const float* vbase = Vt + (((size_t)(b * NKV + (h >> 1))) * SEQ) * HD;

    // load Q tile (64 x 256)
    #pragma unroll
    for (int l = 0; l < 16; l++) {
        int fi = l * 256 + tid;
        int r  = fi >> 6;
        int c4 = fi & 63;
        float4 v4 = *(const float4*)(qbase + (size_t)r * DQK + c4 * 4);
        float* dst = Qs + r * QK_STRIDE + c4 * 4;
        dst[0] = v4.x; dst[1] = v4.y; dst[2] = v4.z; dst[3] = v4.w;
    }

    float m[4], lsum[4], o[4][8];
    #pragma unroll
    for (int i = 0; i < 4; i++) {
        m[i] = -3.0e38f; lsum[i] = 0.0f;
        #pragma unroll
        for (int u = 0; u < 8; u++) o[i][u] = 0.0f;
    }

    const float scale = 0.08838834764831845f;   // 1/sqrt(128)
    const int ntiles = qt + 1;

    for (int kt = 0; kt < ntiles; kt++) {
        const int k0 = kt * FBN;
        __syncthreads();
        // load K tile (64 x 256)
        #pragma unroll
        for (int l = 0; l < 16; l++) {
            int fi = l * 256 + tid;
            int r  = fi >> 6;
            int c4 = fi & 63;
            float4 v4 = *(const float4*)(kbase + (size_t)(k0 + r) * DQK + c4 * 4);
            float* dst = Ks + r * QK_STRIDE + c4 * 4;
            dst[0] = v4.x; dst[1] = v4.y; dst[2] = v4.z; dst[3] = v4.w;
        }
        // load V tile (64 x 128)
        #pragma unroll
        for (int l = 0; l < 8; l++) {
            int fi = l * 256 + tid;
            int r  = fi >> 5;
            int c4 = fi & 31;
            float4 v4 = *(const float4*)(vbase + (size_t)(k0 + r) * HD + c4 * 4);
            float* dst = Vs + r * V_STRIDE + c4 * 4;
            dst[0] = v4.x; dst[1] = v4.y; dst[2] = v4.z; dst[3] = v4.w;
        }
        __syncthreads();

        // S = Q K^T over 256 dims
        float s[4][4];
        #pragma unroll
        for (int i = 0; i < 4; i++)
            #pragma unroll
            for (int j = 0; j < 4; j++) s[i][j] = 0.0f;

        for (int kk = 0; kk < DQK; kk += 4) {
            float4 a[4], bb[4];
            #pragma unroll
            for (int i = 0; i < 4; i++)
                a[i] = *(const float4*)(Qs + (ty + 16 * i) * QK_STRIDE + kk);
            #pragma unroll
            for (int j = 0; j < 4; j++)
                bb[j] = *(const float4*)(Ks + (tx + 16 * j) * QK_STRIDE + kk);
            #pragma unroll
            for (int i = 0; i < 4; i++)
                #pragma unroll
                for (int j = 0; j < 4; j++)
                    s[i][j] += a[i].x * bb[j].x + a[i].y * bb[j].y
                             + a[i].z * bb[j].z + a[i].w * bb[j].w;
        }

        // mask + online softmax
        #pragma unroll
        for (int i = 0; i < 4; i++) {
            const int qi = q0 + ty + 16 * i;
            float mt = -3.0e38f;
            #pragma unroll
            for (int j = 0; j < 4; j++) {
                int kj = k0 + tx + 16 * j;
                float sv = (kj <= qi) ? s[i][j] * scale : -3.0e38f;
                s[i][j] = sv;
                mt = fmaxf(mt, sv);
            }
            #pragma unroll
            for (int off = 1; off < 16; off <<= 1)
                mt = fmaxf(mt, __shfl_xor_sync(0xffffffffu, mt, off));
            float mn = fmaxf(m[i], mt);
            float alpha = expf(m[i] - mn);
            float rs = 0.0f;
            #pragma unroll
            for (int j = 0; j < 4; j++) {
                float p = expf(s[i][j] - mn);
                s[i][j] = p;
                rs += p;
            }
            #pragma unroll
            for (int off = 1; off < 16; off <<= 1)
                rs += __shfl_xor_sync(0xffffffffu, rs, off);
            lsum[i] = lsum[i] * alpha + rs;
            m[i] = mn;
            #pragma unroll
            for (int u = 0; u < 8; u++) o[i][u] *= alpha;
        }

        // stage P through smem
        #pragma unroll
        for (int i = 0; i < 4; i++)
            #pragma unroll
            for (int j = 0; j < 4; j++)
                Ps[(ty + 16 * i) * P_STRIDE + tx + 16 * j] = s[i][j];
        __syncthreads();

        // O += P V
        for (int kk = 0; kk < FBN; kk++) {
            float lp[4];
            #pragma unroll
            for (int i = 0; i < 4; i++)
                lp[i] = Ps[(ty + 16 * i) * P_STRIDE + kk];
            float vv[8];
            #pragma unroll
            for (int u = 0; u < 8; u++)
                vv[u] = Vs[kk * V_STRIDE + tx + 16 * u];
            #pragma unroll
            for (int i = 0; i < 4; i++)
                #pragma unroll
                for (int u = 0; u < 8; u++)
                    o[i][u] += lp[i] * vv[u];
        }
    }

    // epilogue: normalize, write to (B,T, H*hd) layout for the Wo GEMM
    #pragma unroll
    for (int i = 0; i < 4; i++) {
        float inv = 1.0f / lsum[i];
        int t = q0 + ty + 16 * i;
        float* yr = Y + ((size_t)b * SEQ + t) * DM + h * HD;
        #pragma unroll
        for (int u = 0; u < 8; u++)
            yr[tx + 16 * u] = o[i][u] * inv;
    }
}

// ---------------------------------------------------------------------------
// Launch
// ---------------------------------------------------------------------------
extern "C" void kernel_launch(void* const* d_in, const int* in_sizes, int n_in,
                              void* d_out, int out_size)
{
    const float* x     = (const float*)d_in[0];
    const float* Wq    = (const float*)d_in[1];
    const float* Wk    = (const float*)d_in[2];
    const float* Wv    = (const float*)d_in[3];
    const float* Wo    = (const float*)d_in[4];
    const float* delta = (const float*)d_in[5];
    float* out = (float*)d_out;

    float *q_, *k_, *v_, *qe_, *ke_, *vt_, *y_;
    cudaGetSymbolAddress((void**)&q_,  g_q);
    cudaGetSymbolAddress((void**)&k_,  g_k);
    cudaGetSymbolAddress((void**)&v_,  g_v);
    cudaGetSymbolAddress((void**)&qe_, g_qe);
    cudaGetSymbolAddress((void**)&ke_, g_ke);
    cudaGetSymbolAddress((void**)&vt_, g_vt);
    cudaGetSymbolAddress((void**)&y_,  g_y);

    const int M = BSZ * SEQ;   // 4096

    // QKV projections
    sgemm_kernel<<<dim3(DM / 128,        M / 128), 256>>>(x, Wq, q_, M, DM,        DM);
    sgemm_kernel<<<dim3(NKV * HD / 128,  M / 128), 256>>>(x, Wk, k_, M, NKV * HD,  DM);
    sgemm_kernel<<<dim3(NKV * HD / 128,  M / 128), 256>>>(x, Wv, v_, M, NKV * HD,  DM);

    // Phase encode
    {
        const int total = BSZ * NH * SEQ * HD;
        encode_kernel<<<(total + 255) / 256, 256>>>(q_, k_, v_, delta, qe_, ke_, vt_);
    }

    // Flash attention
    {
        size_t smem = (size_t)FLASH_SMEM_FLOATS * sizeof(float);
        cudaFuncSetAttribute(flash_kernel,
                             cudaFuncAttributeMaxDynamicSharedMemorySize,
                             (int)smem);
        flash_kernel<<<dim3(SEQ / FBM, NH, BSZ), 256, smem>>>(qe_, ke_, vt_, y_);
    }

    // Output projection
    sgemm_kernel<<<dim3(DM / 128, M / 128), 256>>>(y_, Wo, out, M, DM, DM);
}

// round 3
// speedup vs baseline: 1.4230x; 1.4230x over previous
#include <cuda_runtime.h>
#include <cuda_bf16.h>
#include <math.h>
#include <stdint.h>

// Problem constants
#define BSZ   2
#define SEQ   2048
#define DM    2048
#define NH    16
#define NKV   8
#define HD    128
#define DQK   256   // concatenated (real,imag) encoding dim

// ---------------------------------------------------------------------------
// Scratch (static __device__ arrays; no allocation allowed)
// ---------------------------------------------------------------------------
__device__ float g_q [BSZ * SEQ * NH  * HD];
__device__ float g_k [BSZ * SEQ * NKV * HD];
__device__ float g_v [BSZ * SEQ * NKV * HD];
__device__ float g_qe[(size_t)BSZ * NH  * SEQ * DQK];
__device__ float g_ke[(size_t)BSZ * NH  * SEQ * DQK];
__device__ float g_vt[(size_t)BSZ * NKV * SEQ * HD];
__device__ float g_y [BSZ * SEQ * NH  * HD];

// ---------------------------------------------------------------------------
// TF32 tensor-core GEMM: C[M,N] = A[M,K] * B[K,N], row-major.
// Requires M%128==0, N%128==0, K%32==0.
// 128x128x32 block tile, 256 threads (8 warps), warp tile 64x32,
// mma.sync.m16n8k8 tf32, cp.async double-buffered pipeline.
// ---------------------------------------------------------------------------
#define GBM 128
#define GBN 128
#define GBK 32
#define ASTR 36     // 32 + 4 pad: bank = (4*r + t) % 32 -> conflict free
#define BSTR 132    // 128 + 4 pad: bank = (4*t + g) % 32 -> conflict free
#define STG_A (GBM * ASTR)
#define STG_B (GBK * BSTR)
#define STG_F (STG_A + STG_B)
#define GEMM_SMEM_BYTES (2 * STG_F * 4)

__device__ __forceinline__ uint32_t f2tf(float x)
{
    uint32_t u;
    asm("cvt.rna.tf32.f32 %0, %1;" : "=r"(u) : "f"(x));
    return u;
}

#define MMA_TF32(d, a, b)                                                     \
    asm volatile(                                                             \
        "mma.sync.aligned.m16n8k8.row.col.f32.tf32.tf32.f32 "                 \
        "{%0,%1,%2,%3},{%4,%5,%6,%7},{%8,%9},{%0,%1,%2,%3};\n"                \
        : "+f"((d)[0]), "+f"((d)[1]), "+f"((d)[2]), "+f"((d)[3])              \
        : "r"((a)[0]), "r"((a)[1]), "r"((a)[2]), "r"((a)[3]),                 \
          "r"((b)[0]), "r"((b)[1]))

__global__ void __launch_bounds__(256)
gemm_tf32_kernel(const float* __restrict__ A, const float* __restrict__ B,
                 float* __restrict__ C, int M, int N, int K)
{
    extern __shared__ float sm[];
    float* Abuf[2] = { sm,         sm + STG_F };
    float* Bbuf[2] = { sm + STG_A, sm + STG_F + STG_A };

    const int tid  = threadIdx.x;
    const int wid  = tid >> 5;
    const int lane = tid & 31;
    const int g    = lane >> 2;   // group id (0..7)
    const int t    = lane & 3;    // thread-in-group (0..3)

    const int wm = wid & 1;       // warp row: 0..1 -> 64 rows each
    const int wn = wid >> 1;      // warp col: 0..3 -> 32 cols each
    const int mbase = wm * 64;
    const int nbase = wn * 32;

    const int bx = blockIdx.x;
    const int by = blockIdx.y;
    const float* Ag = A + (size_t)by * GBM * K;
    const float* Bg = B + (size_t)bx * GBN;

    float acc[4][4][4];
    #pragma unroll
    for (int i = 0; i < 4; i++)
        #pragma unroll
        for (int j = 0; j < 4; j++)
            #pragma unroll
            for (int u = 0; u < 4; u++) acc[i][j][u] = 0.0f;

    const int kiters = K / GBK;

    // chunk decomposition for cp.async (16B each): 1024 chunks per tile,
    // 4 per thread.
    auto issue_stage = [&](int s, int it) {
        const int k0 = it * GBK;
        unsigned sa = (unsigned)__cvta_generic_to_shared(Abuf[s]);
        unsigned sb = (unsigned)__cvta_generic_to_shared(Bbuf[s]);
        #pragma unroll
        for (int c = 0; c < 4; c++) {
            int ch = tid + c * 256;
            // A: row = ch>>3 (0..127), kcol = (ch&7)*4
            int ar = ch >> 3;
            int ak = (ch & 7) * 4;
            const float* srca = Ag + (size_t)ar * K + k0 + ak;
            unsigned dsta = sa + (unsigned)(ar * ASTR + ak) * 4u;
            asm volatile("cp.async.cg.shared.global [%0], [%1], 16;\n"
                         :: "r"(dsta), "l"(srca));
            // B: krow = ch>>5 (0..31), col = (ch&31)*4
            int br = ch >> 5;
            int bc = (ch & 31) * 4;
            const float* srcb = Bg + (size_t)(k0 + br) * N + bc;
            unsigned dstb = sb + (unsigned)(br * BSTR + bc) * 4u;
            asm volatile("cp.async.cg.shared.global [%0], [%1], 16;\n"
                         :: "r"(dstb), "l"(srcb));
        }
        asm volatile("cp.async.commit_group;\n");
    };

    issue_stage(0, 0);

    for (int it = 0; it < kiters; it++) {
        if (it + 1 < kiters)
            issue_stage((it + 1) & 1, it + 1);
        else
            asm volatile("cp.async.commit_group;\n");   // keep group count uniform
        asm volatile("cp.async.wait_group 1;\n");
        __syncthreads();

        const float* as = Abuf[it & 1];
        const float* bs = Bbuf[it & 1];

        #pragma unroll
        for (int kk = 0; kk < 4; kk++) {
            const int k8 = kk * 8;
            uint32_t af[4][4];
            #pragma unroll
            for (int mt = 0; mt < 4; mt++) {
                int r = mbase + mt * 16 + g;
                af[mt][0] = f2tf(as[(size_t)r       * ASTR + k8 + t]);
                af[mt][1] = f2tf(as[(size_t)(r + 8) * ASTR + k8 + t]);
                af[mt][2] = f2tf(as[(size_t)r       * ASTR + k8 + t + 4]);
                af[mt][3] = f2tf(as[(size_t)(r + 8) * ASTR + k8 + t + 4]);
            }
            uint32_t bfm[4][2];
            #pragma unroll
            for (int nt = 0; nt < 4; nt++) {
                int cidx = nbase + nt * 8 + g;
                bfm[nt][0] = f2tf(bs[(size_t)(k8 + t)     * BSTR + cidx]);
                bfm[nt][1] = f2tf(bs[(size_t)(k8 + t + 4) * BSTR + cidx]);
            }
            #pragma unroll
            for (int mt = 0; mt < 4; mt++)
                #pragma unroll
                for (int nt = 0; nt < 4; nt++)
                    MMA_TF32(acc[mt][nt], af[mt], bfm[nt]);
        }
        __syncthreads();
    }

    // epilogue
    #pragma unroll
    for (int mt = 0; mt < 4; mt++) {
        #pragma unroll
        for (int nt = 0; nt < 4; nt++) {
            int row = by * GBM + mbase + mt * 16 + g;
            int col = bx * GBN + nbase + nt * 8 + 2 * t;
            float2 v0 = make_float2(acc[mt][nt][0], acc[mt][nt][1]);
            float2 v1 = make_float2(acc[mt][nt][2], acc[mt][nt][3]);
            *(float2*)(C + (size_t)row * N + col)       = v0;
            *(float2*)(C + (size_t)(row + 8) * N + col) = v1;
        }
    }
}

// ---------------------------------------------------------------------------
// Encode: softplus magnitude * (cos,sin) phase, double-precision range
// reduction (robust regardless of fast-math flags).
// ---------------------------------------------------------------------------
__device__ __forceinline__ float softplusf(float x)
{
    if (x > 20.0f)  return x;
    if (x < -20.0f) return expf(x);
    return log1pf(expf(x));
}

__global__ void encode_kernel(const float* __restrict__ q,
                              const float* __restrict__ k,
                              const float* __restrict__ v,
                              const float* __restrict__ delta,
                              float* __restrict__ qe,
                              float* __restrict__ ke,
                              float* __restrict__ vt)
{
    const int i = blockIdx.x * blockDim.x + threadIdx.x;
    const int total = BSZ * NH * SEQ * HD;
    if (i >= total) return;

    const int d = i & (HD - 1);
    const int t = (i >> 7) & (SEQ - 1);
    const int h = (i >> 18) & (NH - 1);
    const int b = i >> 22;

    const double TWO_PI  = 6.283185307179586;
    const double INV_2PI = 0.15915494309189535;

    const double f   = exp(-9.210340371976184 * (double)d / 128.0);
    const double ang = (double)t * f;

    {
        float qv = q[((size_t)(b * SEQ + t)) * (NH * HD) + h * HD + d];
        float mag = softplusf(qv);
        double ar = ang - floor(ang * INV_2PI) * TWO_PI;
        float sa, ca;
        sincosf((float)ar, &sa, &ca);
        size_t o = (((size_t)(b * NH + h)) * SEQ + t) * DQK + d;
        qe[o]      = mag * ca;
        qe[o + HD] = mag * sa;
    }

    {
        float dl = delta[h * HD + d];
        dl = fminf(fmaxf(dl, -6.2831855f), 0.0f);
        double angk = ang + (double)dl;
        double ar = angk - floor(angk * INV_2PI) * TWO_PI;
        float kv = k[((size_t)(b * SEQ + t)) * (NKV * HD) + (h >> 1) * HD + d];
        float mag = softplusf(kv);
        float sa, ca;
        sincosf((float)ar, &sa, &ca);
        size_t o = (((size_t)(b * NH + h)) * SEQ + t) * DQK + d;
        ke[o]      = mag * ca;
        ke[o + HD] = mag * sa;
    }

    if ((h & 1) == 0) {
        vt[(((size_t)(b * NKV + (h >> 1))) * SEQ + t) * HD + d] =
            v[((size_t)(b * SEQ + t)) * (NKV * HD) + (h >> 1) * HD + d];
    }
}

// ---------------------------------------------------------------------------
// Causal flash attention (fp32 SIMT): d_qk = 256, d_v = 128. BM=BN=64,
// 256 threads, 4x4 score fragment, online softmax.
// ---------------------------------------------------------------------------
#define FBM 64
#define FBN 64
#define QK_STRIDE 260
#define V_STRIDE  129
#define P_STRIDE  68

#define FLASH_SMEM_FLOATS (FBM*QK_STRIDE + FBN*QK_STRIDE + FBN*V_STRIDE + FBM*P_STRIDE)

__global__ void __launch_bounds__(256, 1)
flash_kernel(const float* __restrict__ Qe, const float* __restrict__ Ke,
             const float* __restrict__ Vt, float* __restrict__ Y)
{
    extern __shared__ float smf[];
    float* Qs = smf;
    float* Ks = Qs + FBM * QK_STRIDE;
    float* Vs = Ks + FBN * QK_STRIDE;
    float* Ps = Vs + FBN * V_STRIDE;

    const int qt = blockIdx.x;
    const int h  = blockIdx.y;
    const int b  = blockIdx.z;
    const int q0 = qt * FBM;

    const int tid = threadIdx.x;
    const int tx = tid & 15;
    const int ty = tid >> 4;

    const float* qbase = Qe + (((size_t)(b * NH + h)) * SEQ + q0) * DQK;
    const float* kbase = Ke + (((size_t)(b * NH + h)) * SEQ) * DQK;
    const float* vbase = Vt + (((size_t)(b * NKV + (h >> 1))) * SEQ) * HD;

    #pragma unroll
    for (int l = 0; l < 16; l++) {
        int fi = l * 256 + tid;
        int r  = fi >> 6;
        int c4 = fi & 63;
        float4 v4 = *(const float4*)(qbase + (size_t)r * DQK + c4 * 4);
        float* dst = Qs + r * QK_STRIDE + c4 * 4;
        dst[0] = v4.x; dst[1] = v4.y; dst[2] = v4.z; dst[3] = v4.w;
    }

    float m[4], lsum[4], o[4][8];
    #pragma unroll
    for (int i = 0; i < 4; i++) {
        m[i] = -3.0e38f; lsum[i] = 0.0f;
        #pragma unroll
        for (int u = 0; u < 8; u++) o[i][u] = 0.0f;
    }

    const float scale = 0.08838834764831845f;
    const int ntiles = qt + 1;

    for (int kt = 0; kt < ntiles; kt++) {
        const int k0 = kt * FBN;
        __syncthreads();
        #pragma unroll
        for (int l = 0; l < 16; l++) {
            int fi = l * 256 + tid;
            int r  = fi >> 6;
            int c4 = fi & 63;
            float4 v4 = *(const float4*)(kbase + (size_t)(k0 + r) * DQK + c4 * 4);
            float* dst = Ks + r * QK_STRIDE + c4 * 4;
            dst[0] = v4.x; dst[1] = v4.y; dst[2] = v4.z; dst[3] = v4.w;
        }
        #pragma unroll
        for (int l = 0; l < 8; l++) {
            int fi = l * 256 + tid;
            int r  = fi >> 5;
            int c4 = fi & 31;
            float4 v4 = *(const float4*)(vbase + (size_t)(k0 + r) * HD + c4 * 4);
            float* dst = Vs + r * V_STRIDE + c4 * 4;
            dst[0] = v4.x; dst[1] = v4.y; dst[2] = v4.z; dst[3] = v4.w;
        }
        __syncthreads();

        float s[4][4];
        #pragma unroll
        for (int i = 0; i < 4; i++)
            #pragma unroll
            for (int j = 0; j < 4; j++) s[i][j] = 0.0f;

        for (int kk = 0; kk < DQK; kk += 4) {
            float4 a[4], bb[4];
            #pragma unroll
            for (int i = 0; i < 4; i++)
                a[i] = *(const float4*)(Qs + (ty + 16 * i) * QK_STRIDE + kk);
            #pragma unroll
            for (int j = 0; j < 4; j++)
                bb[j] = *(const float4*)(Ks + (tx + 16 * j) * QK_STRIDE + kk);
            #pragma unroll
            for (int i = 0; i < 4; i++)
                #pragma unroll
                for (int j = 0; j < 4; j++)
                    s[i][j] += a[i].x * bb[j].x + a[i].y * bb[j].y
                             + a[i].z * bb[j].z + a[i].w * bb[j].w;
        }

        #pragma unroll
        for (int i = 0; i < 4; i++) {
            const int qi = q0 + ty + 16 * i;
            float mt = -3.0e38f;
            #pragma unroll
            for (int j = 0; j < 4; j++) {
                int kj = k0 + tx + 16 * j;
                float sv = (kj <= qi) ? s[i][j] * scale : -3.0e38f;
                s[i][j] = sv;
                mt = fmaxf(mt, sv);
            }
            #pragma unroll
            for (int off = 1; off < 16; off <<= 1)
                mt = fmaxf(mt, __shfl_xor_sync(0xffffffffu, mt, off));
            float mn = fmaxf(m[i], mt);
            float alpha = expf(m[i] - mn);
            float rs = 0.0f;
            #pragma unroll
            for (int j = 0; j < 4; j++) {
                float p = expf(s[i][j] - mn);
                s[i][j] = p;
                rs += p;
            }
            #pragma unroll
            for (int off = 1; off < 16; off <<= 1)
                rs += __shfl_xor_sync(0xffffffffu, rs, off);
            lsum[i] = lsum[i] * alpha + rs;
            m[i] = mn;
            #pragma unroll
            for (int u = 0; u < 8; u++) o[i][u] *= alpha;
        }

        #pragma unroll
        for (int i = 0; i < 4; i++)
            #pragma unroll
            for (int j = 0; j < 4; j++)
                Ps[(ty + 16 * i) * P_STRIDE + tx + 16 * j] = s[i][j];
        __syncthreads();

        for (int kk = 0; kk < FBN; kk++) {
            float lp[4];
            #pragma unroll
            for (int i = 0; i < 4; i++)
                lp[i] = Ps[(ty + 16 * i) * P_STRIDE + kk];
            float vv[8];
            #pragma unroll
            for (int u = 0; u < 8; u++)
                vv[u] = Vs[kk * V_STRIDE + tx + 16 * u];
            #pragma unroll
            for (int i = 0; i < 4; i++)
                #pragma unroll
                for (int u = 0; u < 8; u++)
                    o[i][u] += lp[i] * vv[u];
        }
    }

    #pragma unroll
    for (int i = 0; i < 4; i++) {
        float inv = 1.0f / lsum[i];
        int t = q0 + ty + 16 * i;
        float* yr = Y + ((size_t)b * SEQ + t) * DM + h * HD;
        #pragma unroll
        for (int u = 0; u < 8; u++)
            yr[tx + 16 * u] = o[i][u] * inv;
    }
}

// ---------------------------------------------------------------------------
// Launch
// ---------------------------------------------------------------------------
extern "C" void kernel_launch(void* const* d_in, const int* in_sizes, int n_in,
                              void* d_out, int out_size)
{
    const float* x     = (const float*)d_in[0];
    const float* Wq    = (const float*)d_in[1];
    const float* Wk    = (const float*)d_in[2];
    const float* Wv    = (const float*)d_in[3];
    const float* Wo    = (const float*)d_in[4];
    const float* delta = (const float*)d_in[5];
    float* out = (float*)d_out;

    float *q_, *k_, *v_, *qe_, *ke_, *vt_, *y_;
    cudaGetSymbolAddress((void**)&q_,  g_q);
    cudaGetSymbolAddress((void**)&k_,  g_k);
    cudaGetSymbolAddress((void**)&v_,  g_v);
    cudaGetSymbolAddress((void**)&qe_, g_qe);
    cudaGetSymbolAddress((void**)&ke_, g_ke);
    cudaGetSymbolAddress((void**)&vt_, g_vt);
    cudaGetSymbolAddress((void**)&y_,  g_y);

    const int M = BSZ * SEQ;   // 4096

    static bool attr_set = false;
    if (!attr_set) {
        cudaFuncSetAttribute(gemm_tf32_kernel,
                             cudaFuncAttributeMaxDynamicSharedMemorySize,
                             GEMM_SMEM_BYTES);
        cudaFuncSetAttribute(flash_kernel,
                             cudaFuncAttributeMaxDynamicSharedMemorySize,
                             (int)(FLASH_SMEM_FLOATS * sizeof(float)));
        attr_set = true;
    }

    // QKV projections (tf32 tensor core)
    gemm_tf32_kernel<<<dim3(DM / GBN,       M / GBM), 256, GEMM_SMEM_BYTES>>>(
        x, Wq, q_, M, DM, DM);
    gemm_tf32_kernel<<<dim3(NKV * HD / GBN, M / GBM), 256, GEMM_SMEM_BYTES>>>(
        x, Wk, k_, M, NKV * HD, DM);
    gemm_tf32_kernel<<<dim3(NKV * HD / GBN, M / GBM), 256, GEMM_SMEM_BYTES>>>(
        x, Wv, v_, M, NKV * HD, DM);

    // Phase encode
    {
        const int total = BSZ * NH * SEQ * HD;
        encode_kernel<<<(total + 255) / 256, 256>>>(q_, k_, v_, delta, qe_, ke_, vt_);
    }

    // Flash attention
    {
        size_t smem = (size_t)FLASH_SMEM_FLOATS * sizeof(float);
        flash_kernel<<<dim3(SEQ / FBM, NH, BSZ), 256, smem>>>(qe_, ke_, vt_, y_);
    }

    // Output projection (tf32 tensor core)
    gemm_tf32_kernel<<<dim3(DM / GBN, M / GBM), 256, GEMM_SMEM_BYTES>>>(
        y_, Wo, out, M, DM, DM);
}

// round 4
// speedup vs baseline: 2.9498x; 2.0729x over previous
#include <cuda_runtime.h>
#include <cuda_bf16.h>
#include <math.h>
#include <stdint.h>

// Problem constants
#define BSZ   2
#define SEQ   2048
#define DM    2048
#define NH    16
#define NKV   8
#define HD    128
#define DQK   256

// ---------------------------------------------------------------------------
// Scratch
// ---------------------------------------------------------------------------
__device__ float g_q [BSZ * SEQ * NH  * HD];
__device__ float g_k [BSZ * SEQ * NKV * HD];
__device__ float g_v [BSZ * SEQ * NKV * HD];
__device__ float g_qe[(size_t)BSZ * NH  * SEQ * DQK];
__device__ float g_ke[(size_t)BSZ * NH  * SEQ * DQK];
__device__ float g_vt[(size_t)BSZ * NKV * SEQ * HD];
__device__ float g_y [BSZ * SEQ * NH  * HD];
// tf32-pre-rounded copies of inputs
__device__ float g_xr [BSZ * SEQ * DM];
__device__ float g_wq [DM * NH  * HD];
__device__ float g_wk [DM * NKV * HD];
__device__ float g_wv [DM * NKV * HD];
__device__ float g_wo [NH * HD * DM];

__device__ __forceinline__ uint32_t f2tf(float x)
{
    uint32_t u;
    asm("cvt.rna.tf32.f32 %0, %1;" : "=r"(u) : "f"(x));
    return u;
}
__device__ __forceinline__ float f2tf_f(float x)
{
    return __uint_as_float(f2tf(x));
}

#define MMA_TF32(d, a, b)                                                     \
    asm volatile(                                                             \
        "mma.sync.aligned.m16n8k8.row.col.f32.tf32.tf32.f32 "                 \
        "{%0,%1,%2,%3},{%4,%5,%6,%7},{%8,%9},{%0,%1,%2,%3};\n"                \
        : "+f"((d)[0]), "+f"((d)[1]), "+f"((d)[2]), "+f"((d)[3])              \
        : "r"((a)[0]), "r"((a)[1]), "r"((a)[2]), "r"((a)[3]),                 \
          "r"((b)[0]), "r"((b)[1]))

// ---------------------------------------------------------------------------
// Elementwise tf32 rounding pass (n % 4 == 0)
// ---------------------------------------------------------------------------
__global__ void round_tf32_kernel(const float* __restrict__ in,
                                  float* __restrict__ out, int n)
{
    int i = (blockIdx.x * blockDim.x + threadIdx.x) * 4;
    if (i < n) {
        float4 v = *(const float4*)(in + i);
        v.x = f2tf_f(v.x); v.y = f2tf_f(v.y);
        v.z = f2tf_f(v.z); v.w = f2tf_f(v.w);
        *(float4*)(out + i) = v;
    }
}

// ---------------------------------------------------------------------------
// TF32 tensor-core GEMM, inputs pre-rounded. 128x128x32 tile, 256 threads,
// 3-stage cp.async pipeline (depth-2 prefetch). blockIdx.z picks (B,C) pair.
// ---------------------------------------------------------------------------
#define GBM 128
#define GBN 128
#define GBK 32
#define ASTR 36
#define BSTR 132
#define STG_A (GBM * ASTR)
#define STG_B (GBK * BSTR)
#define STG_F (STG_A + STG_B)
#define GEMM_STAGES 3
#define GEMM_SMEM_BYTES (GEMM_STAGES * STG_F * 4)

__global__ void __launch_bounds__(256)
gemm_tf32_kernel(const float* __restrict__ A,
                 const float* __restrict__ B0, float* __restrict__ C0,
                 const float* __restrict__ B1, float* __restrict__ C1,
                 int M, int N, int K)
{
    extern __shared__ float sm[];
    const float* B = blockIdx.z ? B1 : B0;
    float*       C = blockIdx.z ? C1 : C0;

    const int tid  = threadIdx.x;
    const int wid  = tid >> 5;
    const int lane = tid & 31;
    const int g    = lane >> 2;
    const int t    = lane & 3;

    const int wm = wid & 1;
    const int wn = wid >> 1;
    const int mbase = wm * 64;
    const int nbase = wn * 32;

    const int bx = blockIdx.x;
    const int by = blockIdx.y;
    const float* Ag = A + (size_t)by * GBM * K;
    const float* Bg = B + (size_t)bx * GBN;

    float acc[4][4][4];
    #pragma unroll
    for (int i = 0; i < 4; i++)
        #pragma unroll
        for (int j = 0; j < 4; j++)
            #pragma unroll
            for (int u = 0; u < 4; u++) acc[i][j][u] = 0.0f;

    const int kiters = K / GBK;

    auto issue_stage = [&](int s, int it) {
        const int k0 = it * GBK;
        unsigned sa = (unsigned)__cvta_generic_to_shared(sm + s * STG_F);
        unsigned sb = sa + STG_A * 4u;
        #pragma unroll
        for (int c = 0; c < 4; c++) {
            int ch = tid + c * 256;
            int ar = ch >> 3;
            int ak = (ch & 7) * 4;
            const float* srca = Ag + (size_t)ar * K + k0 + ak;
            unsigned dsta = sa + (unsigned)(ar * ASTR + ak) * 4u;
            asm volatile("cp.async.cg.shared.global [%0], [%1], 16;\n"
                         :: "r"(dsta), "l"(srca));
            int br = ch >> 5;
            int bc = (ch & 31) * 4;
            const float* srcb = Bg + (size_t)(k0 + br) * N + bc;
            unsigned dstb = sb + (unsigned)(br * BSTR + bc) * 4u;
            asm volatile("cp.async.cg.shared.global [%0], [%1], 16;\n"
                         :: "r"(dstb), "l"(srcb));
        }
        asm volatile("cp.async.commit_group;\n");
    };

    issue_stage(0, 0);
    issue_stage(1, 1);

    for (int it = 0; it < kiters; it++) {
        if (it + 2 < kiters)
            issue_stage((it + 2) % GEMM_STAGES, it + 2);
        else
            asm volatile("cp.async.commit_group;\n");
        asm volatile("cp.async.wait_group 2;\n");
        __syncthreads();

        const float* as = sm + (it % GEMM_STAGES) * STG_F;
        const float* bs = as + STG_A;

        #pragma unroll
        for (int kk = 0; kk < 4; kk++) {
            const int k8 = kk * 8;
            uint32_t af[4][4];
            #pragma unroll
            for (int mt = 0; mt < 4; mt++) {
                int r = mbase + mt * 16 + g;
                af[mt][0] = __float_as_uint(as[(size_t)r       * ASTR + k8 + t]);
                af[mt][1] = __float_as_uint(as[(size_t)(r + 8) * ASTR + k8 + t]);
                af[mt][2] = __float_as_uint(as[(size_t)r       * ASTR + k8 + t + 4]);
                af[mt][3] = __float_as_uint(as[(size_t)(r + 8) * ASTR + k8 + t + 4]);
            }
            uint32_t bfm[4][2];
            #pragma unroll
            for (int nt = 0; nt < 4; nt++) {
                int cidx = nbase + nt * 8 + g;
                bfm[nt][0] = __float_as_uint(bs[(size_t)(k8 + t)     * BSTR + cidx]);
                bfm[nt][1] = __float_as_uint(bs[(size_t)(k8 + t + 4) * BSTR + cidx]);
            }
            #pragma unroll
            for (int mt = 0; mt < 4; mt++)
                #pragma unroll
                for (int nt = 0; nt < 4; nt++)
                    MMA_TF32(acc[mt][nt], af[mt], bfm[nt]);
        }
        __syncthreads();
    }

    #pragma unroll
    for (int mt = 0; mt < 4; mt++) {
        #pragma unroll
        for (int nt = 0; nt < 4; nt++) {
            int row = by * GBM + mbase + mt * 16 + g;
            int col = bx * GBN + nbase + nt * 8 + 2 * t;
            float2 v0 = make_float2(acc[mt][nt][0], acc[mt][nt][1]);
            float2 v1 = make_float2(acc[mt][nt][2], acc[mt][nt][3]);
            *(float2*)(C + (size_t)row * N + col)       = v0;
            *(float2*)(C + (size_t)(row + 8) * N + col) = v1;
        }
    }
}

// ---------------------------------------------------------------------------
// Encode: softplus magnitude * (cos,sin), double-precision range reduction.
// Outputs pre-rounded to tf32 for the tensor-core flash kernel.
// ---------------------------------------------------------------------------
__device__ __forceinline__ float softplusf(float x)
{
    if (x > 20.0f)  return x;
    if (x < -20.0f) return expf(x);
    return log1pf(expf(x));
}

__global__ void encode_kernel(const float* __restrict__ q,
                              const float* __restrict__ k,
                              const float* __restrict__ v,
                              const float* __restrict__ delta,
                              float* __restrict__ qe,
                              float* __restrict__ ke,
                              float* __restrict__ vt)
{
    const int i = blockIdx.x * blockDim.x + threadIdx.x;
    const int total = BSZ * NH * SEQ * HD;
    if (i >= total) return;

    const int d = i & (HD - 1);
    const int t = (i >> 7) & (SEQ - 1);
    const int h = (i >> 18) & (NH - 1);
    const int b = i >> 22;

    const double TWO_PI  = 6.283185307179586;
    const double INV_2PI = 0.15915494309189535;

    const double f   = exp(-9.210340371976184 * (double)d / 128.0);
    const double ang = (double)t * f;

    {
        float qv = q[((size_t)(b * SEQ + t)) * (NH * HD) + h * HD + d];
        float mag = softplusf(qv);
        double ar = ang - floor(ang * INV_2PI) * TWO_PI;
        float sa, ca;
        sincosf((float)ar, &sa, &ca);
        size_t o = (((size_t)(b * NH + h)) * SEQ + t) * DQK + d;
        qe[o]      = f2tf_f(mag * ca);
        qe[o + HD] = f2tf_f(mag * sa);
    }

    {
        float dl = delta[h * HD + d];
        dl = fminf(fmaxf(dl, -6.2831855f), 0.0f);
        double angk = ang + (double)dl;
        double ar = angk - floor(angk * INV_2PI) * TWO_PI;
        float kv = k[((size_t)(b * SEQ + t)) * (NKV * HD) + (h >> 1) * HD + d];
        float mag = softplusf(kv);
        float sa, ca;
        sincosf((float)ar, &sa, &ca);
        size_t o = (((size_t)(b * NH + h)) * SEQ + t) * DQK + d;
        ke[o]      = f2tf_f(mag * ca);
        ke[o + HD] = f2tf_f(mag * sa);
    }

    if ((h & 1) == 0) {
        float vv = v[((size_t)(b * SEQ + t)) * (NKV * HD) + (h >> 1) * HD + d];
        vt[(((size_t)(b * NKV + (h >> 1))) * SEQ + t) * HD + d] = f2tf_f(vv);
    }
}

// ---------------------------------------------------------------------------
// Tensor-core causal flash attention.
// BM=64, BN=32, 128 threads (4 warps), warp tile 16 rows x 32 cols.
// QK over 256 dims + PV via mma.sync tf32. Double-buffered cp.async K/V.
// All inputs pre-rounded to tf32; P rounded before PV; y rounded on store.
// ---------------------------------------------------------------------------
#define FBM 64
#define FBN 32
#define QSTR 260   // % 32 == 4 -> conflict-free fragment LDS
#define KSTR 260
#define VSTR 136   // % 32 == 8 -> conflict-free
#define PSTR 36    // % 32 == 4

#define FL_Q_F (FBM * QSTR)
#define FL_K_F (2 * FBN * KSTR)
#define FL_V_F (2 * FBN * VSTR)
#define FL_P_F (FBM * PSTR)
#define FLASH_SMEM_BYTES ((FL_Q_F + FL_K_F + FL_V_F + FL_P_F) * 4)

__global__ void __launch_bounds__(128, 1)
flash_tc_kernel(const float* __restrict__ Qe, const float* __restrict__ Ke,
                const float* __restrict__ Vt, float* __restrict__ Y)
{
    extern __shared__ float smf[];
    float* Qs  = smf;
    float* Ks0 = Qs  + FL_Q_F;
    float* Vs0 = Ks0 + FL_K_F;
    float* Ps  = Vs0 + FL_V_F;

    const int qt = blockIdx.x;
    const int h  = blockIdx.y;
    const int b  = blockIdx.z;
    const int q0 = qt * FBM;

    const int tid  = threadIdx.x;
    const int wid  = tid >> 5;
    const int lane = tid & 31;
    const int g    = lane >> 2;
    const int t    = lane & 3;
    const int r0   = wid * 16;

    const float* qbase = Qe + (((size_t)(b * NH + h)) * SEQ + q0) * DQK;
    const float* kbase = Ke + (((size_t)(b * NH + h)) * SEQ) * DQK;
    const float* vbase = Vt + (((size_t)(b * NKV + (h >> 1))) * SEQ) * HD;

    // Q tile 64x256 (one-time)
    #pragma unroll
    for (int l = 0; l < 32; l++) {
        int i = l * 128 + tid;
        int r = i >> 6;
        int c = (i & 63) * 4;
        float4 v4 = *(const float4*)(qbase + (size_t)r * DQK + c);
        *(float4*)(Qs + r * QSTR + c) = v4;
    }

    auto issue_kv = [&](int s, int kt) {
        const int k0 = kt * FBN;
        unsigned ks = (unsigned)__cvta_generic_to_shared(Ks0 + s * FBN * KSTR);
        unsigned vs = (unsigned)__cvta_generic_to_shared(Vs0 + s * FBN * VSTR);
        #pragma unroll
        for (int l = 0; l < 16; l++) {       // K: 32x256 = 2048 chunks
            int i = l * 128 + tid;
            int r = i >> 6;
            int c = (i & 63) * 4;
            const float* src = kbase + (size_t)(k0 + r) * DQK + c;
            unsigned dst = ks + (unsigned)(r * KSTR + c) * 4u;
            asm volatile("cp.async.cg.shared.global [%0], [%1], 16;\n"
                         :: "r"(dst), "l"(src));
        }
        #pragma unroll
        for (int l = 0; l < 8; l++) {        // V: 32x128 = 1024 chunks
            int i = l * 128 + tid;
            int r = i >> 5;
            int c = (i & 31) * 4;
            const float* src = vbase + (size_t)(k0 + r) * HD + c;
            unsigned dst = vs + (unsigned)(r * VSTR + c) * 4u;
            asm volatile("cp.async.cg.shared.global [%0], [%1], 16;\n"
                         :: "r"(dst), "l"(src));
        }
        asm volatile("cp.async.commit_group;\n");
    };

    float m[2]    = { -3.0e38f, -3.0e38f };
    float lsum[2] = { 0.0f, 0.0f };
    float oacc[16][4];
    #pragma unroll
    for (int j = 0; j < 16; j++)
        #pragma unroll
        for (int u = 0; u < 4; u++) oacc[j][u] = 0.0f;

    const float scale = 0.08838834764831845f;  // 1/sqrt(128)
    const int nt = 2 * qt + 2;

    issue_kv(0, 0);

    for (int kt = 0; kt < nt; kt++) {
        const int k0 = kt * FBN;
        if (kt + 1 < nt)
            issue_kv((kt + 1) & 1, kt + 1);
        else
            asm volatile("cp.async.commit_group;\n");
        asm volatile("cp.async.wait_group 1;\n");
        __syncthreads();

        const float* Ksb = Ks0 + (kt & 1) * FBN * KSTR;
        const float* Vsb = Vs0 + (kt & 1) * FBN * VSTR;

        // ---- S = Q K^T (16x32 per warp, k=256) ----
        float sacc[4][4];
        #pragma unroll
        for (int j = 0; j < 4; j++)
            #pragma unroll
            for (int u = 0; u < 4; u++) sacc[j][u] = 0.0f;

        #pragma unroll
        for (int ks = 0; ks < 32; ks++) {
            const int k8 = ks * 8;
            uint32_t a[4];
            a[0] = __float_as_uint(Qs[(r0 + g)     * QSTR + k8 + t]);
            a[1] = __float_as_uint(Qs[(r0 + g + 8) * QSTR + k8 + t]);
            a[2] = __float_as_uint(Qs[(r0 + g)     * QSTR + k8 + t + 4]);
            a[3] = __float_as_uint(Qs[(r0 + g + 8) * QSTR + k8 + t + 4]);
            #pragma unroll
            for (int j = 0; j < 4; j++) {
                uint32_t bb[2];
                bb[0] = __float_as_uint(Ksb[(8 * j + g) * KSTR + k8 + t]);
                bb[1] = __float_as_uint(Ksb[(8 * j + g) * KSTR + k8 + t + 4]);
                MMA_TF32(sacc[j], a, bb);
            }
        }

        // ---- online softmax (rows g and g+8, warp-local) ----
        const bool diag = (kt >= 2 * qt);
        #pragma unroll
        for (int half = 0; half < 2; half++) {
            const int row = q0 + r0 + g + 8 * half;
            float v[8];
            float mloc = -3.0e38f;
            #pragma unroll
            for (int j = 0; j < 4; j++) {
                #pragma unroll
                for (int c = 0; c < 2; c++) {
                    int col = k0 + 8 * j + 2 * t + c;
                    float sv = sacc[j][2 * half + c] * scale;
                    if (diag && col > row) sv = -3.0e38f;
                    v[2 * j + c] = sv;
                    mloc = fmaxf(mloc, sv);
                }
            }
            mloc = fmaxf(mloc, __shfl_xor_sync(0xffffffffu, mloc, 1));
            mloc = fmaxf(mloc, __shfl_xor_sync(0xffffffffu, mloc, 2));
            float mn = fmaxf(m[half], mloc);
            float alpha = __expf(m[half] - mn);
            float rs = 0.0f;
            #pragma unroll
            for (int u = 0; u < 8; u++) {
                float p = __expf(v[u] - mn);
                v[u] = p;
                rs += p;
            }
            rs += __shfl_xor_sync(0xffffffffu, rs, 1);
            rs += __shfl_xor_sync(0xffffffffu, rs, 2);
            lsum[half] = lsum[half] * alpha + rs;
            m[half] = mn;
            #pragma unroll
            for (int j = 0; j < 16; j++) {
                oacc[j][2 * half]     *= alpha;
                oacc[j][2 * half + 1] *= alpha;
            }
            // store P (tf32-rounded)
            #pragma unroll
            for (int j = 0; j < 4; j++) {
                float2 pv;
                pv.x = f2tf_f(v[2 * j]);
                pv.y = f2tf_f(v[2 * j + 1]);
                *(float2*)(Ps + (r0 + g + 8 * half) * PSTR + 8 * j + 2 * t) = pv;
            }
        }
        __syncwarp();

        // ---- O += P V (16x128 per warp, k=32) ----
        #pragma unroll
        for (int ks = 0; ks < 4; ks++) {
            const int k8 = ks * 8;
            uint32_t a[4];
            a[0] = __float_as_uint(Ps[(r0 + g)     * PSTR + k8 + t]);
            a[1] = __float_as_uint(Ps[(r0 + g + 8) * PSTR + k8 + t]);
            a[2] = __float_as_uint(Ps[(r0 + g)     * PSTR + k8 + t + 4]);
            a[3] = __float_as_uint(Ps[(r0 + g + 8) * PSTR + k8 + t + 4]);
            #pragma unroll
            for (int j = 0; j < 16; j++) {
                uint32_t bb[2];
                bb[0] = __float_as_uint(Vsb[(k8 + t)     * VSTR + 8 * j + g]);
                bb[1] = __float_as_uint(Vsb[(k8 + t + 4) * VSTR + 8 * j + g]);
                MMA_TF32(oacc[j], a, bb);
            }
        }
        __syncthreads();
    }

    // epilogue: normalize, tf32-round, write (B,T,H*hd) for the Wo GEMM
    #pragma unroll
    for (int half = 0; half < 2; half++) {
        const int row = q0 + r0 + g + 8 * half;
        const float inv = 1.0f / lsum[half];
        float* yr = Y + ((size_t)b * SEQ + row) * DM + h * HD;
        #pragma unroll
        for (int j = 0; j < 16; j++) {
            float2 o2;
            o2.x = f2tf_f(oacc[j][2 * half]     * inv);
            o2.y = f2tf_f(oacc[j][2 * half + 1] * inv);
            *(float2*)(yr + 8 * j + 2 * t) = o2;
        }
    }
}

// ---------------------------------------------------------------------------
// Launch
// ---------------------------------------------------------------------------
extern "C" void kernel_launch(void* const* d_in, const int* in_sizes, int n_in,
                              void* d_out, int out_size)
{
    const float* x     = (const float*)d_in[0];
    const float* Wq    = (const float*)d_in[1];
    const float* Wk    = (const float*)d_in[2];
    const float* Wv    = (const float*)d_in[3];
    const float* Wo    = (const float*)d_in[4];
    const float* delta = (const float*)d_in[5];
    float* out = (float*)d_out;

    float *q_, *k_, *v_, *qe_, *ke_, *vt_, *y_;
    float *xr_, *wq_, *wk_, *wv_, *wo_;
    cudaGetSymbolAddress((void**)&q_,  g_q);
    cudaGetSymbolAddress((void**)&k_,  g_k);
    cudaGetSymbolAddress((void**)&v_,  g_v);
    cudaGetSymbolAddress((void**)&qe_, g_qe);
    cudaGetSymbolAddress((void**)&ke_, g_ke);
    cudaGetSymbolAddress((void**)&vt_, g_vt);
    cudaGetSymbolAddress((void**)&y_,  g_y);
    cudaGetSymbolAddress((void**)&xr_, g_xr);
    cudaGetSymbolAddress((void**)&wq_, g_wq);
    cudaGetSymbolAddress((void**)&wk_, g_wk);
    cudaGetSymbolAddress((void**)&wv_, g_wv);
    cudaGetSymbolAddress((void**)&wo_, g_wo);

    const int M = BSZ * SEQ;   // 4096

    static bool attr_set = false;
    if (!attr_set) {
        cudaFuncSetAttribute(gemm_tf32_kernel,
                             cudaFuncAttributeMaxDynamicSharedMemorySize,
                             GEMM_SMEM_BYTES);
        cudaFuncSetAttribute(flash_tc_kernel,
                             cudaFuncAttributeMaxDynamicSharedMemorySize,
                             FLASH_SMEM_BYTES);
        attr_set = true;
    }

    // tf32 pre-rounding passes
    {
        int n;
        n = BSZ * SEQ * DM;
        round_tf32_kernel<<<(n / 4 + 255) / 256, 256>>>(x,  xr_, n);
        n = DM * NH * HD;
        round_tf32_kernel<<<(n / 4 + 255) / 256, 256>>>(Wq, wq_, n);
        n = DM * NKV * HD;
        round_tf32_kernel<<<(n / 4 + 255) / 256, 256>>>(Wk, wk_, n);
        round_tf32_kernel<<<(n / 4 + 255) / 256, 256>>>(Wv, wv_, n);
        n = NH * HD * DM;
        round_tf32_kernel<<<(n / 4 + 255) / 256, 256>>>(Wo, wo_, n);
    }

    // Q projection
    gemm_tf32_kernel<<<dim3(DM / GBN, M / GBM, 1), 256, GEMM_SMEM_BYTES>>>(
        xr_, wq_, q_, wq_, q_, M, DM, DM);
    // K and V projections fused via blockIdx.z
    gemm_tf32_kernel<<<dim3(NKV * HD / GBN, M / GBM, 2), 256, GEMM_SMEM_BYTES>>>(
        xr_, wk_, k_, wv_, v_, M, NKV * HD, DM);

    // Phase encode (outputs tf32-rounded)
    {
        const int total = BSZ * NH * SEQ * HD;
        encode_kernel<<<(total + 255) / 256, 256>>>(q_, k_, v_, delta, qe_, ke_, vt_);
    }

    // Tensor-core flash attention
    flash_tc_kernel<<<dim3(SEQ / FBM, NH, BSZ), 128, FLASH_SMEM_BYTES>>>(
        qe_, ke_, vt_, y_);

    // Output projection
    gemm_tf32_kernel<<<dim3(DM / GBN, M / GBM, 1), 256, GEMM_SMEM_BYTES>>>(
        y_, wo_, out, wo_, out, M, DM, DM);
}

// round 6
// speedup vs baseline: 4.7825x; 1.6213x over previous
#include <cuda_runtime.h>
#include <cuda_fp16.h>
#include <math.h>
#include <stdint.h>

// Problem constants
#define BSZ   2
#define SEQ   2048
#define DM    2048
#define NH    16
#define NKV   8
#define HD    128
#define DQK   256

// ---------------------------------------------------------------------------
// Scratch (static __device__ arrays)
// ---------------------------------------------------------------------------
__device__ float  g_q [BSZ * SEQ * NH  * HD];
__device__ float  g_k [BSZ * SEQ * NKV * HD];
__device__ float  g_v [BSZ * SEQ * NKV * HD];
__device__ __half g_qe[(size_t)BSZ * NH  * SEQ * DQK];
__device__ __half g_ke[(size_t)BSZ * NH  * SEQ * DQK];
__device__ __half g_vt[(size_t)BSZ * NKV * HD * SEQ];   // [b][kvh][d][T]
__device__ __half g_yh[BSZ * SEQ * NH * HD];
// half-converted inputs; weights TRANSPOSED to [N][K]
__device__ __half g_xh [BSZ * SEQ * DM];
__device__ __half g_wq [NH  * HD * DM];
__device__ __half g_wk [NKV * HD * DM];
__device__ __half g_wv [NKV * HD * DM];
__device__ __half g_wo [DM * NH * HD];

// fp16 mma m16n8k16, fp32 accum
#define MMA_F16(d, a, b)                                                      \
    asm volatile(                                                             \
        "mma.sync.aligned.m16n8k16.row.col.f32.f16.f16.f32 "                  \
        "{%0,%1,%2,%3},{%4,%5,%6,%7},{%8,%9},{%0,%1,%2,%3};\n"                \
        : "+f"((d)[0]), "+f"((d)[1]), "+f"((d)[2]), "+f"((d)[3])              \
        : "r"((a)[0]), "r"((a)[1]), "r"((a)[2]), "r"((a)[3]),                 \
          "r"((b)[0]), "r"((b)[1]))

__device__ __forceinline__ uint32_t ld_h2(const __half* p)
{
    return *(const uint32_t*)p;
}

// ---------------------------------------------------------------------------
// float -> half conversion (n % 4 == 0)
// ---------------------------------------------------------------------------
__global__ void f2h_kernel(const float* __restrict__ in,
                           __half* __restrict__ out, int n)
{
    int i = (blockIdx.x * blockDim.x + threadIdx.x) * 4;
    if (i < n) {
        float4 v = *(const float4*)(in + i);
        __half2 h0 = __floats2half2_rn(v.x, v.y);
        __half2 h1 = __floats2half2_rn(v.z, v.w);
        uint2 u;
        u.x = *(uint32_t*)&h0;
        u.y = *(uint32_t*)&h1;
        *(uint2*)(out + i) = u;
    }
}

// W [K][N] f32 -> Wt [N][K] half
__global__ void transpose_h_kernel(const float* __restrict__ in,
                                   __half* __restrict__ out, int K, int N)
{
    __shared__ float tile[32][33];
    const int n0 = blockIdx.x * 32;
    const int k0 = blockIdx.y * 32;
    const int tx = threadIdx.x;
    const int ty = threadIdx.y;   // block (32, 8)
    #pragma unroll
    for (int j = 0; j < 32; j += 8)
        tile[ty + j][tx] = in[(size_t)(k0 + ty + j) * N + n0 + tx];
    __syncthreads();
    #pragma unroll
    for (int j = 0; j < 32; j += 8)
        out[(size_t)(n0 + ty + j) * K + k0 + tx] = __float2half(tile[tx][ty + j]);
}

// v f32 [b][t][kvh*128+d] -> vt half [b][kvh][d][T]
__global__ void vtrans_kernel(const float* __restrict__ v,
                              __half* __restrict__ vt)
{
    __shared__ float tile[32][33];
    const int t0 = blockIdx.x * 32;
    const int d0 = blockIdx.y * 32;
    const int z  = blockIdx.z;        // b * NKV + kh
    const int b  = z / NKV;
    const int kh = z % NKV;
    const int tx = threadIdx.x;
    const int ty = threadIdx.y;       // block (32, 8)
    #pragma unroll
    for (int j = 0; j < 32; j += 8)
        tile[ty + j][tx] =
            v[((size_t)(b * SEQ + t0 + ty + j)) * (NKV * HD) + kh * HD + d0 + tx];
    __syncthreads();
    #pragma unroll
    for (int j = 0; j < 32; j += 8)
        vt[((size_t)(b * NKV + kh) * HD + d0 + ty + j) * SEQ + t0 + tx] =
            __float2half(tile[tx][ty + j]);
}

// ---------------------------------------------------------------------------
// fp16 tensor-core GEMM: C[M,N] = Ah[M,K] * Bt[N,K]^T (f32 out).
// 128x128x32 tile, 256 threads (8 warps, warp tile 64x32), 3-stage cp.async.
// blockIdx.z selects (B0,C0)/(B1,C1).
// ---------------------------------------------------------------------------
#define GASTR 40                        // halves; 80 bytes, 16B-aligned rows
#define G_STG_H (2 * 128 * GASTR)       // A + B halves per stage
#define G_STAGES 3
#define GEMM_SMEM_BYTES (G_STAGES * G_STG_H * 2)

__global__ void __launch_bounds__(256)
gemm_h_kernel(const __half* __restrict__ A,
              const __half* __restrict__ B0, float* __restrict__ C0,
              const __half* __restrict__ B1, float* __restrict__ C1,
              int M, int N, int K)
{
    extern __shared__ __half smh[];

    const __half* B = blockIdx.z ? B1 : B0;
    float*        C = blockIdx.z ? C1 : C0;

    const int tid  = threadIdx.x;
    const int wid  = tid >> 5;
    const int lane = tid & 31;
    const int g    = lane >> 2;
    const int t    = lane & 3;

    const int mbase = (wid & 1) * 64;
    const int nbase = (wid >> 1) * 32;

    const __half* Ag = A + (size_t)blockIdx.y * 128 * K;
    const __half* Bg = B + (size_t)blockIdx.x * 128 * K;

    float acc[4][4][4];
    #pragma unroll
    for (int i = 0; i < 4; i++)
        #pragma unroll
        for (int j = 0; j < 4; j++)
            #pragma unroll
            for (int u = 0; u < 4; u++) acc[i][j][u] = 0.0f;

    const int kiters = K / 32;

    auto issue_stage = [&](int s, int it) {
        const int k0 = it * 32;
        unsigned sa = (unsigned)__cvta_generic_to_shared(smh + s * G_STG_H);
        unsigned sb = sa + 128u * GASTR * 2u;
        #pragma unroll
        for (int j = 0; j < 2; j++) {
            int c = tid + j * 256;              // 0..511
            int r  = c >> 2;                    // 0..127
            int ch = (c & 3) * 8;               // half offset
            const __half* srca = Ag + (size_t)r * K + k0 + ch;
            asm volatile("cp.async.cg.shared.global [%0], [%1], 16;\n"
                         :: "r"(sa + (unsigned)(r * GASTR + ch) * 2u), "l"(srca));
            const __half* srcb = Bg + (size_t)r * K + k0 + ch;
            asm volatile("cp.async.cg.shared.global [%0], [%1], 16;\n"
                         :: "r"(sb + (unsigned)(r * GASTR + ch) * 2u), "l"(srcb));
        }
        asm volatile("cp.async.commit_group;\n");
    };

    issue_stage(0, 0);
    issue_stage(1, 1);

    for (int it = 0; it < kiters; it++) {
        if (it + 2 < kiters)
            issue_stage((it + 2) % G_STAGES, it + 2);
        else
            asm volatile("cp.async.commit_group;\n");
        asm volatile("cp.async.wait_group 2;\n");
        __syncthreads();

        const __half* as = smh + (it % G_STAGES) * G_STG_H;
        const __half* bs = as + 128 * GASTR;

        #pragma unroll
        for (int ks = 0; ks < 2; ks++) {
            const int kk = ks * 16;
            uint32_t af[4][4];
            #pragma unroll
            for (int mt = 0; mt < 4; mt++) {
                const __half* ar0 = as + (size_t)(mbase + mt * 16 + g) * GASTR + kk;
                const __half* ar1 = ar0 + 8 * GASTR;
                af[mt][0] = ld_h2(ar0 + 2 * t);
                af[mt][1] = ld_h2(ar1 + 2 * t);
                af[mt][2] = ld_h2(ar0 + 2 * t + 8);
                af[mt][3] = ld_h2(ar1 + 2 * t + 8);
            }
            uint32_t bf[4][2];
            #pragma unroll
            for (int nt = 0; nt < 4; nt++) {
                const __half* br = bs + (size_t)(nbase + nt * 8 + g) * GASTR + kk;
                bf[nt][0] = ld_h2(br + 2 * t);
                bf[nt][1] = ld_h2(br + 2 * t + 8);
            }
            #pragma unroll
            for (int mt = 0; mt < 4; mt++)
                #pragma unroll
                for (int nt = 0; nt < 4; nt++)
                    MMA_F16(acc[mt][nt], af[mt], bf[nt]);
        }
        __syncthreads();
    }

    #pragma unroll
    for (int mt = 0; mt < 4; mt++) {
        #pragma unroll
        for (int nt = 0; nt < 4; nt++) {
            int row = blockIdx.y * 128 + mbase + mt * 16 + g;
            int col = blockIdx.x * 128 + nbase + nt * 8 + 2 * t;
            *(float2*)(C + (size_t)row * N + col) =
                make_float2(acc[mt][nt][0], acc[mt][nt][1]);
            *(float2*)(C + (size_t)(row + 8) * N + col) =
                make_float2(acc[mt][nt][2], acc[mt][nt][3]);
        }
    }
}

// ---------------------------------------------------------------------------
// Encode: softplus magnitude * (cos,sin), double-precision range reduction.
// Outputs half qe/ke.
// ---------------------------------------------------------------------------
__device__ __forceinline__ float softplusf(float x)
{
    if (x > 20.0f)  return x;
    if (x < -20.0f) return expf(x);
    return log1pf(expf(x));
}

__global__ void encode_kernel(const float* __restrict__ q,
                              const float* __restrict__ k,
                              const float* __restrict__ delta,
                              __half* __restrict__ qe,
                              __half* __restrict__ ke)
{
    const int i = blockIdx.x * blockDim.x + threadIdx.x;
    const int total = BSZ * NH * SEQ * HD;
    if (i >= total) return;

    const int d = i & (HD - 1);
    const int t = (i >> 7) & (SEQ - 1);
    const int h = (i >> 18) & (NH - 1);
    const int b = i >> 22;

    const double TWO_PI  = 6.283185307179586;
    const double INV_2PI = 0.15915494309189535;

    const double f   = exp(-9.210340371976184 * (double)d / 128.0);
    const double ang = (double)t * f;

    {
        float qv = q[((size_t)(b * SEQ + t)) * (NH * HD) + h * HD + d];
        float mag = softplusf(qv);
        double ar = ang - floor(ang * INV_2PI) * TWO_PI;
        float sa, ca;
        sincosf((float)ar, &sa, &ca);
        size_t o = (((size_t)(b * NH + h)) * SEQ + t) * DQK + d;
        qe[o]      = __float2half(mag * ca);
        qe[o + HD] = __float2half(mag * sa);
    }

    {
        float dl = delta[h * HD + d];
        dl = fminf(fmaxf(dl, -6.2831855f), 0.0f);
        double angk = ang + (double)dl;
        double ar = angk - floor(angk * INV_2PI) * TWO_PI;
        float kv = k[((size_t)(b * SEQ + t)) * (NKV * HD) + (h >> 1) * HD + d];
        float mag = softplusf(kv);
        float sa, ca;
        sincosf((float)ar, &sa, &ca);
        size_t o = (((size_t)(b * NH + h)) * SEQ + t) * DQK + d;
        ke[o]      = __float2half(mag * ca);
        ke[o + HD] = __float2half(mag * sa);
    }
}

// ---------------------------------------------------------------------------
// fp16 tensor-core causal flash attention.
// BM=64, BN=32, 128 threads (4 warps, 16 rows each). QK k=256, PV k=32.
// V pre-transposed [d][T]. Double-buffered cp.async K/V.
// ---------------------------------------------------------------------------
#define FBM 64
#define FBN 32
#define QSTR 264    // halves; 528B rows, 16B aligned; banks g*4+t
#define KSTR 264
#define VSTR 40     // banks g*20+t
#define PSTR 40

#define FL_Q_H (FBM * QSTR)
#define FL_K_H (2 * FBN * KSTR)
#define FL_V_H (2 * HD * VSTR)
#define FL_P_H (FBM * PSTR)
#define FLASH_SMEM_BYTES ((FL_Q_H + FL_K_H + FL_V_H + FL_P_H) * 2)

__global__ void __launch_bounds__(128)
flash_h_kernel(const __half* __restrict__ Qe, const __half* __restrict__ Ke,
               const __half* __restrict__ Vt, __half* __restrict__ Y)
{
    extern __shared__ __half smh[];
    __half* Qs  = smh;
    __half* Ks0 = Qs  + FL_Q_H;
    __half* Vs0 = Ks0 + FL_K_H;
    __half* Ps  = Vs0 + FL_V_H;

    const int qt = blockIdx.x;
    const int h  = blockIdx.y;
    const int b  = blockIdx.z;
    const int q0 = qt * FBM;

    const int tid  = threadIdx.x;
    const int wid  = tid >> 5;
    const int lane = tid & 31;
    const int g    = lane >> 2;
    const int t    = lane & 3;
    const int r0   = wid * 16;

    const __half* qbase = Qe + (((size_t)(b * NH + h)) * SEQ + q0) * DQK;
    const __half* kbase = Ke + (((size_t)(b * NH + h)) * SEQ) * DQK;
    const __half* vbase = Vt + ((size_t)(b * NKV + (h >> 1)) * HD) * SEQ;

    // Q tile 64x256 halves = 2048 16B chunks, 16/thread
    {
        unsigned qs = (unsigned)__cvta_generic_to_shared(Qs);
        #pragma unroll
        for (int l = 0; l < 16; l++) {
            int i = l * 128 + tid;
            int r  = i >> 5;
            int c8 = (i & 31) * 8;
            const __half* src = qbase + (size_t)r * DQK + c8;
            asm volatile("cp.async.cg.shared.global [%0], [%1], 16;\n"
                         :: "r"(qs + (unsigned)(r * QSTR + c8) * 2u), "l"(src));
        }
        asm volatile("cp.async.commit_group;\n");
    }

    auto issue_kv = [&](int s, int kt) {
        const int k0 = kt * FBN;
        unsigned ks = (unsigned)__cvta_generic_to_shared(Ks0 + s * FBN * KSTR);
        unsigned vs = (unsigned)__cvta_generic_to_shared(Vs0 + s * HD * VSTR);
        #pragma unroll
        for (int l = 0; l < 8; l++) {       // K: 32x256 halves = 1024 chunks
            int i = l * 128 + tid;
            int r  = i >> 5;
            int c8 = (i & 31) * 8;
            const __half* src = kbase + (size_t)(k0 + r) * DQK + c8;
            asm volatile("cp.async.cg.shared.global [%0], [%1], 16;\n"
                         :: "r"(ks + (unsigned)(r * KSTR + c8) * 2u), "l"(src));
        }
        #pragma unroll
        for (int l = 0; l < 4; l++) {       // V: 128 d x 32 t halves = 512 chunks
            int i = l * 128 + tid;
            int rd = i >> 2;
            int c8 = (i & 3) * 8;
            const __half* src = vbase + (size_t)rd * SEQ + k0 + c8;
            asm volatile("cp.async.cg.shared.global [%0], [%1], 16;\n"
                         :: "r"(vs + (unsigned)(rd * VSTR + c8) * 2u), "l"(src));
        }
        asm volatile("cp.async.commit_group;\n");
    };

    float m[2]    = { -3.0e38f, -3.0e38f };
    float lsum[2] = { 0.0f, 0.0f };
    float oacc[16][4];
    #pragma unroll
    for (int j = 0; j < 16; j++)
        #pragma unroll
        for (int u = 0; u < 4; u++) oacc[j][u] = 0.0f;

    const float scale = 0.08838834764831845f;   // 1/sqrt(128)
    const int nt = 2 * qt + 2;

    issue_kv(0, 0);

    for (int kt = 0; kt < nt; kt++) {
        const int k0 = kt * FBN;
        if (kt + 1 < nt)
            issue_kv((kt + 1) & 1, kt + 1);
        else
            asm volatile("cp.async.commit_group;\n");
        asm volatile("cp.async.wait_group 1;\n");
        __syncthreads();

        const __half* Ksb = Ks0 + (kt & 1) * FBN * KSTR;
        const __half* Vsb = Vs0 + (kt & 1) * HD * VSTR;

        // ---- S = Q K^T (16x32 per warp, k=256, 16 k16 steps) ----
        float sacc[4][4];
        #pragma unroll
        for (int j = 0; j < 4; j++)
            #pragma unroll
            for (int u = 0; u < 4; u++) sacc[j][u] = 0.0f;

        #pragma unroll
        for (int ks = 0; ks < 16; ks++) {
            const int kk = ks * 16;
            uint32_t a[4];
            const __half* ar0 = Qs + (size_t)(r0 + g) * QSTR + kk;
            const __half* ar1 = ar0 + 8 * QSTR;
            a[0] = ld_h2(ar0 + 2 * t);
            a[1] = ld_h2(ar1 + 2 * t);
            a[2] = ld_h2(ar0 + 2 * t + 8);
            a[3] = ld_h2(ar1 + 2 * t + 8);
            #pragma unroll
            for (int j = 0; j < 4; j++) {
                const __half* br = Ksb + (size_t)(8 * j + g) * KSTR + kk;
                uint32_t bb[2];
                bb[0] = ld_h2(br + 2 * t);
                bb[1] = ld_h2(br + 2 * t + 8);
                MMA_F16(sacc[j], a, bb);
            }
        }

        // ---- online softmax (rows g, g+8; warp-local) ----
        const bool diag = (kt >= 2 * qt);
        #pragma unroll
        for (int half = 0; half < 2; half++) {
            const int row = q0 + r0 + g + 8 * half;
            float v[8];
            float mloc = -3.0e38f;
            #pragma unroll
            for (int j = 0; j < 4; j++) {
                #pragma unroll
                for (int c = 0; c < 2; c++) {
                    int col = k0 + 8 * j + 2 * t + c;
                    float sv = sacc[j][2 * half + c] * scale;
                    if (diag && col > row) sv = -3.0e38f;
                    v[2 * j + c] = sv;
                    mloc = fmaxf(mloc, sv);
                }
            }
            mloc = fmaxf(mloc, __shfl_xor_sync(0xffffffffu, mloc, 1));
            mloc = fmaxf(mloc, __shfl_xor_sync(0xffffffffu, mloc, 2));
            float mn = fmaxf(m[half], mloc);
            float alpha = __expf(m[half] - mn);
            float rs = 0.0f;
            __half2 ph[4];
            #pragma unroll
            for (int j = 0; j < 4; j++) {
                float p0 = __expf(v[2 * j]     - mn);
                float p1 = __expf(v[2 * j + 1] - mn);
                __half2 h2 = __floats2half2_rn(p0, p1);
                ph[j] = h2;
                float2 pr = __half22float2(h2);
                rs += pr.x + pr.y;
            }
            rs += __shfl_xor_sync(0xffffffffu, rs, 1);
            rs += __shfl_xor_sync(0xffffffffu, rs, 2);
            lsum[half] = lsum[half] * alpha + rs;
            m[half] = mn;
            #pragma unroll
            for (int j = 0; j < 16; j++) {
                oacc[j][2 * half]     *= alpha;
                oacc[j][2 * half + 1] *= alpha;
            }
            #pragma unroll
            for (int j = 0; j < 4; j++)
                *(__half2*)(Ps + (size_t)(r0 + g + 8 * half) * PSTR
                            + 8 * j + 2 * t) = ph[j];
        }
        __syncwarp();

        // ---- O += P V (16x128 per warp, k=32, 2 k16 steps) ----
        #pragma unroll
        for (int ks = 0; ks < 2; ks++) {
            const int kk = ks * 16;
            uint32_t a[4];
            const __half* ar0 = Ps + (size_t)(r0 + g) * PSTR + kk;
            const __half* ar1 = ar0 + 8 * PSTR;
            a[0] = ld_h2(ar0 + 2 * t);
            a[1] = ld_h2(ar1 + 2 * t);
            a[2] = ld_h2(ar0 + 2 * t + 8);
            a[3] = ld_h2(ar1 + 2 * t + 8);
            #pragma unroll
            for (int j = 0; j < 16; j++) {
                const __half* br = Vsb + (size_t)(8 * j + g) * VSTR + kk;
                uint32_t bb[2];
                bb[0] = ld_h2(br + 2 * t);
                bb[1] = ld_h2(br + 2 * t + 8);
                MMA_F16(oacc[j], a, bb);
            }
        }
        __syncthreads();
    }

    // epilogue: normalize, write half y (B,T,H*hd) for the Wo GEMM
    #pragma unroll
    for (int half = 0; half < 2; half++) {
        const int row = q0 + r0 + g + 8 * half;
        const float inv = 1.0f / lsum[half];
        __half* yr = Y + ((size_t)b * SEQ + row) * DM + h * HD;
        #pragma unroll
        for (int j = 0; j < 16; j++)
            *(__half2*)(yr + 8 * j + 2 * t) =
                __floats2half2_rn(oacc[j][2 * half] * inv,
                                  oacc[j][2 * half + 1] * inv);
    }
}

// ---------------------------------------------------------------------------
// Launch
// ---------------------------------------------------------------------------
extern "C" void kernel_launch(void* const* d_in, const int* in_sizes, int n_in,
                              void* d_out, int out_size)
{
    const float* x     = (const float*)d_in[0];
    const float* Wq    = (const float*)d_in[1];
    const float* Wk    = (const float*)d_in[2];
    const float* Wv    = (const float*)d_in[3];
    const float* Wo    = (const float*)d_in[4];
    const float* delta = (const float*)d_in[5];
    float* out = (float*)d_out;

    float  *q_, *k_, *v_;
    __half *qe_, *ke_, *vt_, *yh_, *xh_, *wq_, *wk_, *wv_, *wo_;
    cudaGetSymbolAddress((void**)&q_,  g_q);
    cudaGetSymbolAddress((void**)&k_,  g_k);
    cudaGetSymbolAddress((void**)&v_,  g_v);
    cudaGetSymbolAddress((void**)&qe_, g_qe);
    cudaGetSymbolAddress((void**)&ke_, g_ke);
    cudaGetSymbolAddress((void**)&vt_, g_vt);
    cudaGetSymbolAddress((void**)&yh_, g_yh);
    cudaGetSymbolAddress((void**)&xh_, g_xh);
    cudaGetSymbolAddress((void**)&wq_, g_wq);
    cudaGetSymbolAddress((void**)&wk_, g_wk);
    cudaGetSymbolAddress((void**)&wv_, g_wv);
    cudaGetSymbolAddress((void**)&wo_, g_wo);

    const int M = BSZ * SEQ;   // 4096

    cudaFuncSetAttribute(gemm_h_kernel,
                         cudaFuncAttributeMaxDynamicSharedMemorySize,
                         GEMM_SMEM_BYTES);
    cudaFuncSetAttribute(flash_h_kernel,
                         cudaFuncAttributeMaxDynamicSharedMemorySize,
                         FLASH_SMEM_BYTES);

    // half conversion (x) + transpose-convert (weights -> [N][K])
    {
        int n = BSZ * SEQ * DM;
        f2h_kernel<<<(n / 4 + 255) / 256, 256>>>(x, xh_, n);
        dim3 blk(32, 8);
        transpose_h_kernel<<<dim3(DM / 32,       DM / 32), blk>>>(Wq, wq_, DM, DM);
        transpose_h_kernel<<<dim3(NKV * HD / 32, DM / 32), blk>>>(Wk, wk_, DM, NKV * HD);
        transpose_h_kernel<<<dim3(NKV * HD / 32, DM / 32), blk>>>(Wv, wv_, DM, NKV * HD);
        transpose_h_kernel<<<dim3(DM / 32,       DM / 32), blk>>>(Wo, wo_, DM, DM);
    }

    // Q projection
    gemm_h_kernel<<<dim3(DM / 128, M / 128, 1), 256, GEMM_SMEM_BYTES>>>(
        xh_, wq_, q_, wq_, q_, M, DM, DM);
    // K and V projections fused via blockIdx.z
    gemm_h_kernel<<<dim3(NKV * HD / 128, M / 128, 2), 256, GEMM_SMEM_BYTES>>>(
        xh_, wk_, k_, wv_, v_, M, NKV * HD, DM);

    // Phase encode + V transpose (f32 -> half [d][T])
    {
        const int total = BSZ * NH * SEQ * HD;
        encode_kernel<<<(total + 255) / 256, 256>>>(q_, k_, delta, qe_, ke_);
        vtrans_kernel<<<dim3(SEQ / 32, HD / 32, BSZ * NKV), dim3(32, 8)>>>(v_, vt_);
    }

    // Flash attention (fp16 mma)
    flash_h_kernel<<<dim3(SEQ / FBM, NH, BSZ), 128, FLASH_SMEM_BYTES>>>(
        qe_, ke_, vt_, yh_);

    // Output projection
    gemm_h_kernel<<<dim3(DM / 128, M / 128, 1), 256, GEMM_SMEM_BYTES>>>(
        yh_, wo_, out, wo_, out, M, DM, DM);
}

// round 7
// speedup vs baseline: 5.3052x; 1.1093x over previous
#include <cuda_runtime.h>
#include <cuda_fp16.h>
#include <math.h>
#include <stdint.h>

// Problem constants
#define BSZ   2
#define SEQ   2048
#define DM    2048
#define NH    16
#define NKV   8
#define HD    128
#define DQK   256

// ---------------------------------------------------------------------------
// Scratch
// ---------------------------------------------------------------------------
__device__ float  g_q [BSZ * SEQ * NH  * HD];
__device__ float  g_k [BSZ * SEQ * NKV * HD];
__device__ float  g_v [BSZ * SEQ * NKV * HD];
__device__ __half g_qe[(size_t)BSZ * NH  * SEQ * DQK];
__device__ __half g_ke[(size_t)BSZ * NH  * SEQ * DQK];
__device__ __half g_vt[(size_t)BSZ * NKV * HD * SEQ];   // [b][kvh][d][T]
__device__ __half g_yh[BSZ * SEQ * NH * HD];
__device__ __half g_xh [BSZ * SEQ * DM];
__device__ __half g_wq [NH  * HD * DM];
__device__ __half g_wk [NKV * HD * DM];
__device__ __half g_wv [NKV * HD * DM];
__device__ __half g_wo [DM * NH * HD];
// phase tables
__device__ float g_cs [SEQ * HD];
__device__ float g_sn [SEQ * HD];
__device__ float g_cd [NH * HD];
__device__ float g_sd [NH * HD];

#define MMA_F16(d, a, b)                                                      \
    asm volatile(                                                             \
        "mma.sync.aligned.m16n8k16.row.col.f32.f16.f16.f32 "                  \
        "{%0,%1,%2,%3},{%4,%5,%6,%7},{%8,%9},{%0,%1,%2,%3};\n"                \
        : "+f"((d)[0]), "+f"((d)[1]), "+f"((d)[2]), "+f"((d)[3])              \
        : "r"((a)[0]), "r"((a)[1]), "r"((a)[2]), "r"((a)[3]),                 \
          "r"((b)[0]), "r"((b)[1]))

#define LDSM_X4(r0, r1, r2, r3, addr)                                         \
    asm volatile("ldmatrix.sync.aligned.m8n8.x4.shared.b16 "                  \
                 "{%0,%1,%2,%3}, [%4];"                                       \
                 : "=r"(r0), "=r"(r1), "=r"(r2), "=r"(r3) : "r"(addr))

// ---------------------------------------------------------------------------
// Prep kernels
// ---------------------------------------------------------------------------
__global__ void f2h_kernel(const float* __restrict__ in,
                           __half* __restrict__ out, int n)
{
    int i = (blockIdx.x * blockDim.x + threadIdx.x) * 4;
    if (i < n) {
        float4 v = *(const float4*)(in + i);
        __half2 h0 = __floats2half2_rn(v.x, v.y);
        __half2 h1 = __floats2half2_rn(v.z, v.w);
        uint2 u;
        u.x = *(uint32_t*)&h0;
        u.y = *(uint32_t*)&h1;
        *(uint2*)(out + i) = u;
    }
}

// W [K][N] f32 -> Wt [N][K] half
__global__ void transpose_h_kernel(const float* __restrict__ in,
                                   __half* __restrict__ out, int K, int N)
{
    __shared__ float tile[32][33];
    const int n0 = blockIdx.x * 32;
    const int k0 = blockIdx.y * 32;
    const int tx = threadIdx.x;
    const int ty = threadIdx.y;   // block (32, 8)
    #pragma unroll
    for (int j = 0; j < 32; j += 8)
        tile[ty + j][tx] = in[(size_t)(k0 + ty + j) * N + n0 + tx];
    __syncthreads();
    #pragma unroll
    for (int j = 0; j < 32; j += 8)
        out[(size_t)(n0 + ty + j) * K + k0 + tx] = __float2half(tile[tx][ty + j]);
}

// v f32 [b][t][kvh*128+d] -> vt half [b][kvh][d][T]
__global__ void vtrans_kernel(const float* __restrict__ v,
                              __half* __restrict__ vt)
{
    __shared__ float tile[32][33];
    const int t0 = blockIdx.x * 32;
    const int d0 = blockIdx.y * 32;
    const int z  = blockIdx.z;
    const int b  = z / NKV;
    const int kh = z % NKV;
    const int tx = threadIdx.x;
    const int ty = threadIdx.y;   // block (32, 8)
    #pragma unroll
    for (int j = 0; j < 32; j += 8)
        tile[ty + j][tx] =
            v[((size_t)(b * SEQ + t0 + ty + j)) * (NKV * HD) + kh * HD + d0 + tx];
    __syncthreads();
    #pragma unroll
    for (int j = 0; j < 32; j += 8)
        vt[((size_t)(b * NKV + kh) * HD + d0 + ty + j) * SEQ + t0 + tx] =
            __float2half(tile[tx][ty + j]);
}

// base angle table: cos/sin(t * freq(d)), double range reduction
__global__ void angles_kernel(float* __restrict__ cs, float* __restrict__ sn)
{
    const int i = blockIdx.x * blockDim.x + threadIdx.x;
    if (i >= SEQ * HD) return;
    const int d = i & (HD - 1);
    const int t = i >> 7;
    const double TWO_PI  = 6.283185307179586;
    const double INV_2PI = 0.15915494309189535;
    const double f   = exp(-9.210340371976184 * (double)d / 128.0);
    const double ang = (double)t * f;
    const double ar  = ang - floor(ang * INV_2PI) * TWO_PI;
    float sa, ca;
    sincosf((float)ar, &sa, &ca);
    cs[i] = ca;
    sn[i] = sa;
}

__global__ void delta_kernel(const float* __restrict__ delta,
                             float* __restrict__ cd, float* __restrict__ sd)
{
    const int i = blockIdx.x * blockDim.x + threadIdx.x;
    if (i >= NH * HD) return;
    float dl = delta[i];
    dl = fminf(fmaxf(dl, -6.2831855f), 0.0f);
    float s, c;
    sincosf(dl, &s, &c);
    cd[i] = c;
    sd[i] = s;
}

// ---------------------------------------------------------------------------
// Encode: softplus magnitude * phase (table-driven, no trig)
// ---------------------------------------------------------------------------
__device__ __forceinline__ float softplus_fast(float x)
{
    if (x > 15.0f) return x;
    return __logf(1.0f + __expf(x));
}

__global__ void encode_kernel(const float* __restrict__ q,
                              const float* __restrict__ k,
                              const float* __restrict__ cs,
                              const float* __restrict__ sn,
                              const float* __restrict__ cd,
                              const float* __restrict__ sd,
                              __half* __restrict__ qe,
                              __half* __restrict__ ke)
{
    const int i = blockIdx.x * blockDim.x + threadIdx.x;
    const int total = BSZ * NH * SEQ * HD;
    if (i >= total) return;

    const int d = i & (HD - 1);
    const int t = (i >> 7) & (SEQ - 1);
    const int h = (i >> 18) & (NH - 1);
    const int b = i >> 22;

    const float ca = cs[(t << 7) + d];
    const float sa = sn[(t << 7) + d];

    {
        float qv  = q[((size_t)(b * SEQ + t)) * (NH * HD) + h * HD + d];
        float mag = softplus_fast(qv);
        size_t o = (((size_t)(b * NH + h)) * SEQ + t) * DQK + d;
        qe[o]      = __float2half(mag * ca);
        qe[o + HD] = __float2half(mag * sa);
    }

    {
        const float c = cd[(h << 7) + d];
        const float s = sd[(h << 7) + d];
        const float ck = ca * c - sa * s;
        const float sk = sa * c + ca * s;
        float kv  = k[((size_t)(b * SEQ + t)) * (NKV * HD) + (h >> 1) * HD + d];
        float mag = softplus_fast(kv);
        size_t o = (((size_t)(b * NH + h)) * SEQ + t) * DQK + d;
        ke[o]      = __float2half(mag * ck);
        ke[o + HD] = __float2half(mag * sk);
    }
}

// ---------------------------------------------------------------------------
// fp16 tensor-core GEMM with ldmatrix fragment loads.
// C[M,N] = Ah[M,K] * Bt[N,K]^T. 128x128x32 tile, 256 threads, 3-stage cp.async.
// ---------------------------------------------------------------------------
#define GASTR 40
#define G_STG_H (2 * 128 * GASTR)
#define G_STAGES 3
#define GEMM_SMEM_BYTES (G_STAGES * G_STG_H * 2)

__global__ void __launch_bounds__(256)
gemm_h_kernel(const __half* __restrict__ A,
              const __half* __restrict__ B0, float* __restrict__ C0,
              const __half* __restrict__ B1, float* __restrict__ C1,
              int M, int N, int K)
{
    extern __shared__ __half smh[];

    const __half* B = blockIdx.z ? B1 : B0;
    float*        C = blockIdx.z ? C1 : C0;

    const int tid    = threadIdx.x;
    const int wid    = tid >> 5;
    const int lane   = tid & 31;
    const int g      = lane >> 2;
    const int t      = lane & 3;
    const int lane15 = lane & 15;
    const int lanehi = (lane >> 4) * 8;

    const int mbase = (wid & 1) * 64;
    const int nbase = (wid >> 1) * 32;

    const __half* Ag = A + (size_t)blockIdx.y * 128 * K;
    const __half* Bg = B + (size_t)blockIdx.x * 128 * K;

    const uint32_t smb = (uint32_t)__cvta_generic_to_shared(smh);
    // ldmatrix per-lane row offsets (in halves)
    const uint32_t a_off = (uint32_t)((mbase + lane15) * GASTR + lanehi);
    const uint32_t b_off = (uint32_t)((nbase + lane15) * GASTR + lanehi);

    float acc[4][4][4];
    #pragma unroll
    for (int i = 0; i < 4; i++)
        #pragma unroll
        for (int j = 0; j < 4; j++)
            #pragma unroll
            for (int u = 0; u < 4; u++) acc[i][j][u] = 0.0f;

    const int kiters = K / 32;

    auto issue_stage = [&](int s, int it) {
        const int k0 = it * 32;
        unsigned sa = smb + (unsigned)s * (G_STG_H * 2u);
        unsigned sb = sa + 128u * GASTR * 2u;
        #pragma unroll
        for (int j = 0; j < 2; j++) {
            int c = tid + j * 256;
            int r  = c >> 2;
            int ch = (c & 3) * 8;
            const __half* srca = Ag + (size_t)r * K + k0 + ch;
            asm volatile("cp.async.cg.shared.global [%0], [%1], 16;\n"
                         :: "r"(sa + (unsigned)(r * GASTR + ch) * 2u), "l"(srca));
            const __half* srcb = Bg + (size_t)r * K + k0 + ch;
            asm volatile("cp.async.cg.shared.global [%0], [%1], 16;\n"
                         :: "r"(sb + (unsigned)(r * GASTR + ch) * 2u), "l"(srcb));
        }
        asm volatile("cp.async.commit_group;\n");
    };

    issue_stage(0, 0);
    issue_stage(1, 1);

    for (int it = 0; it < kiters; it++) {
        if (it + 2 < kiters)
            issue_stage((it + 2) % G_STAGES, it + 2);
        else
            asm volatile("cp.async.commit_group;\n");
        asm volatile("cp.async.wait_group 2;\n");
        __syncthreads();

        const uint32_t sa = smb + (uint32_t)(it % G_STAGES) * (G_STG_H * 2u);
        const uint32_t sb = sa + 128u * GASTR * 2u;

        #pragma unroll
        for (int ks = 0; ks < 2; ks++) {
            const int kk = ks * 16;
            uint32_t af[4][4];
            #pragma unroll
            for (int mt = 0; mt < 4; mt++)
                LDSM_X4(af[mt][0], af[mt][1], af[mt][2], af[mt][3],
                        sa + (a_off + mt * 16 * GASTR + kk) * 2u);
            uint32_t bf[4][2];
            #pragma unroll
            for (int p = 0; p < 2; p++) {
                uint32_t r0, r1, r2, r3;
                LDSM_X4(r0, r1, r2, r3,
                        sb + (b_off + p * 16 * GASTR + kk) * 2u);
                bf[2 * p][0]     = r0;
                bf[2 * p + 1][0] = r1;
                bf[2 * p][1]     = r2;
                bf[2 * p + 1][1] = r3;
            }
            #pragma unroll
            for (int mt = 0; mt < 4; mt++)
                #pragma unroll
                for (int nt = 0; nt < 4; nt++)
                    MMA_F16(acc[mt][nt], af[mt], bf[nt]);
        }
        __syncthreads();
    }

    #pragma unroll
    for (int mt = 0; mt < 4; mt++) {
        #pragma unroll
        for (int nt = 0; nt < 4; nt++) {
            int row = blockIdx.y * 128 + mbase + mt * 16 + g;
            int col = blockIdx.x * 128 + nbase + nt * 8 + 2 * t;
            *(float2*)(C + (size_t)row * N + col) =
                make_float2(acc[mt][nt][0], acc[mt][nt][1]);
            *(float2*)(C + (size_t)(row + 8) * N + col) =
                make_float2(acc[mt][nt][2], acc[mt][nt][3]);
        }
    }
}

// ---------------------------------------------------------------------------
// fp16 tensor-core causal flash attention with ldmatrix.
// BM=64, BN=32, 128 threads. QK k=256, PV k=32. V pre-transposed [d][T].
// ---------------------------------------------------------------------------
#define FBM 64
#define FBN 32
#define QSTR 264
#define KSTR 264
#define VSTR 40
#define PSTR 40

#define FL_Q_H (FBM * QSTR)
#define FL_K_H (2 * FBN * KSTR)
#define FL_V_H (2 * HD * VSTR)
#define FL_P_H (FBM * PSTR)
#define FLASH_SMEM_BYTES ((FL_Q_H + FL_K_H + FL_V_H + FL_P_H) * 2)

__global__ void __launch_bounds__(128)
flash_h_kernel(const __half* __restrict__ Qe, const __half* __restrict__ Ke,
               const __half* __restrict__ Vt, __half* __restrict__ Y)
{
    extern __shared__ __half smh[];
    __half* Qs  = smh;
    __half* Ks0 = Qs  + FL_Q_H;
    __half* Vs0 = Ks0 + FL_K_H;
    __half* Ps  = Vs0 + FL_V_H;

    const int qt = blockIdx.x;
    const int h  = blockIdx.y;
    const int b  = blockIdx.z;
    const int q0 = qt * FBM;

    const int tid    = threadIdx.x;
    const int wid    = tid >> 5;
    const int lane   = tid & 31;
    const int g      = lane >> 2;
    const int t      = lane & 3;
    const int lane15 = lane & 15;
    const int lanehi = (lane >> 4) * 8;
    const int r0     = wid * 16;

    const __half* qbase = Qe + (((size_t)(b * NH + h)) * SEQ + q0) * DQK;
    const __half* kbase = Ke + (((size_t)(b * NH + h)) * SEQ) * DQK;
    const __half* vbase = Vt + ((size_t)(b * NKV + (h >> 1)) * HD) * SEQ;

    const uint32_t smb   = (uint32_t)__cvta_generic_to_shared(smh);
    const uint32_t qs_b  = smb;
    const uint32_t ks_b  = smb + FL_Q_H * 2u;
    const uint32_t vs_b  = smb + (FL_Q_H + FL_K_H) * 2u;
    const uint32_t ps_b  = smb + (FL_Q_H + FL_K_H + FL_V_H) * 2u;

    const uint32_t q_off = (uint32_t)((r0 + lane15) * QSTR + lanehi);
    const uint32_t k_off = (uint32_t)(lane15 * KSTR + lanehi);
    const uint32_t v_off = (uint32_t)(lane15 * VSTR + lanehi);
    const uint32_t p_off = (uint32_t)((r0 + lane15) * PSTR + lanehi);

    // Q tile
    {
        #pragma unroll
        for (int l = 0; l < 16; l++) {
            int i = l * 128 + tid;
            int r  = i >> 5;
            int c8 = (i & 31) * 8;
            const __half* src = qbase + (size_t)r * DQK + c8;
            asm volatile("cp.async.cg.shared.global [%0], [%1], 16;\n"
                         :: "r"(qs_b + (unsigned)(r * QSTR + c8) * 2u), "l"(src));
        }
        asm volatile("cp.async.commit_group;\n");
    }

    auto issue_kv = [&](int s, int kt) {
        const int k0 = kt * FBN;
        unsigned ks = ks_b + (unsigned)s * (FBN * KSTR * 2u);
        unsigned vs = vs_b + (unsigned)s * (HD * VSTR * 2u);
        #pragma unroll
        for (int l = 0; l < 8; l++) {
            int i = l * 128 + tid;
            int r  = i >> 5;
            int c8 = (i & 31) * 8;
            const __half* src = kbase + (size_t)(k0 + r) * DQK + c8;
            asm volatile("cp.async.cg.shared.global [%0], [%1], 16;\n"
                         :: "r"(ks + (unsigned)(r * KSTR + c8) * 2u), "l"(src));
        }
        #pragma unroll
        for (int l = 0; l < 4; l++) {
            int i = l * 128 + tid;
            int rd = i >> 2;
            int c8 = (i & 3) * 8;
            const __half* src = vbase + (size_t)rd * SEQ + k0 + c8;
            asm volatile("cp.async.cg.shared.global [%0], [%1], 16;\n"
                         :: "r"(vs + (unsigned)(rd * VSTR + c8) * 2u), "l"(src));
        }
        asm volatile("cp.async.commit_group;\n");
    };

    float m[2]    = { -3.0e38f, -3.0e38f };
    float lsum[2] = { 0.0f, 0.0f };
    float oacc[16][4];
    #pragma unroll
    for (int j = 0; j < 16; j++)
        #pragma unroll
        for (int u = 0; u < 4; u++) oacc[j][u] = 0.0f;

    const float scale = 0.08838834764831845f;
    const int nt = 2 * qt + 2;

    issue_kv(0, 0);

    for (int kt = 0; kt < nt; kt++) {
        const int k0 = kt * FBN;
        if (kt + 1 < nt)
            issue_kv((kt + 1) & 1, kt + 1);
        else
            asm volatile("cp.async.commit_group;\n");
        asm volatile("cp.async.wait_group 1;\n");
        __syncthreads();

        const uint32_t ksb = ks_b + (uint32_t)(kt & 1) * (FBN * KSTR * 2u);
        const uint32_t vsb = vs_b + (uint32_t)(kt & 1) * (HD * VSTR * 2u);

        // ---- S = Q K^T ----
        float sacc[4][4];
        #pragma unroll
        for (int j = 0; j < 4; j++)
            #pragma unroll
            for (int u = 0; u < 4; u++) sacc[j][u] = 0.0f;

        #pragma unroll
        for (int ks = 0; ks < 16; ks++) {
            const int kk = ks * 16;
            uint32_t a[4];
            LDSM_X4(a[0], a[1], a[2], a[3], qs_b + (q_off + kk) * 2u);
            uint32_t bf[4][2];
            #pragma unroll
            for (int p = 0; p < 2; p++) {
                uint32_t r0r, r1r, r2r, r3r;
                LDSM_X4(r0r, r1r, r2r, r3r,
                        ksb + (k_off + p * 16 * KSTR + kk) * 2u);
                bf[2 * p][0]     = r0r;
                bf[2 * p + 1][0] = r1r;
                bf[2 * p][1]     = r2r;
                bf[2 * p + 1][1] = r3r;
            }
            #pragma unroll
            for (int j = 0; j < 4; j++)
                MMA_F16(sacc[j], a, bf[j]);
        }

        // ---- online softmax ----
        const bool diag = (kt >= 2 * qt);
        #pragma unroll
        for (int half = 0; half < 2; half++) {
            const int row = q0 + r0 + g + 8 * half;
            float v[8];
            float mloc = -3.0e38f;
            #pragma unroll
            for (int j = 0; j < 4; j++) {
                #pragma unroll
                for (int c = 0; c < 2; c++) {
                    int col = k0 + 8 * j + 2 * t + c;
                    float sv = sacc[j][2 * half + c] * scale;
                    if (diag && col > row) sv = -3.0e38f;
                    v[2 * j + c] = sv;
                    mloc = fmaxf(mloc, sv);
                }
            }
            mloc = fmaxf(mloc, __shfl_xor_sync(0xffffffffu, mloc, 1));
            mloc = fmaxf(mloc, __shfl_xor_sync(0xffffffffu, mloc, 2));
            float mn = fmaxf(m[half], mloc);
            float alpha = __expf(m[half] - mn);
            float rs = 0.0f;
            __half2 ph[4];
            #pragma unroll
            for (int j = 0; j < 4; j++) {
                float p0 = __expf(v[2 * j]     - mn);
                float p1 = __expf(v[2 * j + 1] - mn);
                __half2 h2 = __floats2half2_rn(p0, p1);
                ph[j] = h2;
                float2 pr = __half22float2(h2);
                rs += pr.x + pr.y;
            }
            rs += __shfl_xor_sync(0xffffffffu, rs, 1);
            rs += __shfl_xor_sync(0xffffffffu, rs, 2);
            lsum[half] = lsum[half] * alpha + rs;
            m[half] = mn;
            #pragma unroll
            for (int j = 0; j < 16; j++) {
                oacc[j][2 * half]     *= alpha;
                oacc[j][2 * half + 1] *= alpha;
            }
            #pragma unroll
            for (int j = 0; j < 4; j++)
                *(__half2*)(Ps + (size_t)(r0 + g + 8 * half) * PSTR
                            + 8 * j + 2 * t) = ph[j];
        }
        __syncwarp();

        // ---- O += P V ----
        #pragma unroll
        for (int ks = 0; ks < 2; ks++) {
            const int kk = ks * 16;
            uint32_t a[4];
            LDSM_X4(a[0], a[1], a[2], a[3], ps_b + (p_off + kk) * 2u);
            #pragma unroll
            for (int p = 0; p < 8; p++) {
                uint32_t r0r, r1r, r2r, r3r;
                LDSM_X4(r0r, r1r, r2r, r3r,
                        vsb + (v_off + p * 16 * VSTR + kk) * 2u);
                uint32_t b0[2] = { r0r, r2r };
                uint32_t b1[2] = { r1r, r3r };
                MMA_F16(oacc[2 * p],     a, b0);
                MMA_F16(oacc[2 * p + 1], a, b1);
            }
        }
        __syncthreads();
    }

    // epilogue
    #pragma unroll
    for (int half = 0; half < 2; half++) {
        const int row = q0 + r0 + g + 8 * half;
        const float inv = 1.0f / lsum[half];
        __half* yr = Y + ((size_t)b * SEQ + row) * DM + h * HD;
        #pragma unroll
        for (int j = 0; j < 16; j++)
            *(__half2*)(yr + 8 * j + 2 * t) =
                __floats2half2_rn(oacc[j][2 * half] * inv,
                                  oacc[j][2 * half + 1] * inv);
    }
}

// ---------------------------------------------------------------------------
// Launch
// ---------------------------------------------------------------------------
extern "C" void kernel_launch(void* const* d_in, const int* in_sizes, int n_in,
                              void* d_out, int out_size)
{
    const float* x     = (const float*)d_in[0];
    const float* Wq    = (const float*)d_in[1];
    const float* Wk    = (const float*)d_in[2];
    const float* Wv    = (const float*)d_in[3];
    const float* Wo    = (const float*)d_in[4];
    const float* delta = (const float*)d_in[5];
    float* out = (float*)d_out;

    float  *q_, *k_, *v_, *cs_, *sn_, *cd_, *sd_;
    __half *qe_, *ke_, *vt_, *yh_, *xh_, *wq_, *wk_, *wv_, *wo_;
    cudaGetSymbolAddress((void**)&q_,  g_q);
    cudaGetSymbolAddress((void**)&k_,  g_k);
    cudaGetSymbolAddress((void**)&v_,  g_v);
    cudaGetSymbolAddress((void**)&qe_, g_qe);
    cudaGetSymbolAddress((void**)&ke_, g_ke);
    cudaGetSymbolAddress((void**)&vt_, g_vt);
    cudaGetSymbolAddress((void**)&yh_, g_yh);
    cudaGetSymbolAddress((void**)&xh_, g_xh);
    cudaGetSymbolAddress((void**)&wq_, g_wq);
    cudaGetSymbolAddress((void**)&wk_, g_wk);
    cudaGetSymbolAddress((void**)&wv_, g_wv);
    cudaGetSymbolAddress((void**)&wo_, g_wo);
    cudaGetSymbolAddress((void**)&cs_, g_cs);
    cudaGetSymbolAddress((void**)&sn_, g_sn);
    cudaGetSymbolAddress((void**)&cd_, g_cd);
    cudaGetSymbolAddress((void**)&sd_, g_sd);

    const int M = BSZ * SEQ;   // 4096

    cudaFuncSetAttribute(gemm_h_kernel,
                         cudaFuncAttributeMaxDynamicSharedMemorySize,
                         GEMM_SMEM_BYTES);
    cudaFuncSetAttribute(flash_h_kernel,
                         cudaFuncAttributeMaxDynamicSharedMemorySize,
                         FLASH_SMEM_BYTES);

    // prep: conversions, transposes, phase tables
    {
        int n = BSZ * SEQ * DM;
        f2h_kernel<<<(n / 4 + 255) / 256, 256>>>(x, xh_, n);
        dim3 blk(32, 8);
        transpose_h_kernel<<<dim3(DM / 32,       DM / 32), blk>>>(Wq, wq_, DM, DM);
        transpose_h_kernel<<<dim3(NKV * HD / 32, DM / 32), blk>>>(Wk, wk_, DM, NKV * HD);
        transpose_h_kernel<<<dim3(NKV * HD / 32, DM / 32), blk>>>(Wv, wv_, DM, NKV * HD);
        transpose_h_kernel<<<dim3(DM / 32,       DM / 32), blk>>>(Wo, wo_, DM, DM);
        angles_kernel<<<(SEQ * HD + 255) / 256, 256>>>(cs_, sn_);
        delta_kernel<<<(NH * HD + 255) / 256, 256>>>(delta, cd_, sd_);
    }

    // projections
    gemm_h_kernel<<<dim3(DM / 128, M / 128, 1), 256, GEMM_SMEM_BYTES>>>(
        xh_, wq_, q_, wq_, q_, M, DM, DM);
    gemm_h_kernel<<<dim3(NKV * HD / 128, M / 128, 2), 256, GEMM_SMEM_BYTES>>>(
        xh_, wk_, k_, wv_, v_, M, NKV * HD, DM);

    // encode + V transpose
    {
        const int total = BSZ * NH * SEQ * HD;
        encode_kernel<<<(total + 255) / 256, 256>>>(q_, k_, cs_, sn_, cd_, sd_,
                                                    qe_, ke_);
        vtrans_kernel<<<dim3(SEQ / 32, HD / 32, BSZ * NKV), dim3(32, 8)>>>(v_, vt_);
    }

    // flash attention
    flash_h_kernel<<<dim3(SEQ / FBM, NH, BSZ), 128, FLASH_SMEM_BYTES>>>(
        qe_, ke_, vt_, yh_);

    // output projection
    gemm_h_kernel<<<dim3(DM / 128, M / 128, 1), 256, GEMM_SMEM_BYTES>>>(
        yh_, wo_, out, wo_, out, M, DM, DM);
}

// round 11
// speedup vs baseline: 5.7243x; 1.0790x over previous
#include <cuda_runtime.h>
#include <cuda_fp16.h>
#include <math.h>
#include <stdint.h>

// Problem constants
#define BSZ   2
#define SEQ   2048
#define DM    2048
#define NH    16
#define NKV   8
#define HD    128
#define DQK   256

// ---------------------------------------------------------------------------
// Scratch
// ---------------------------------------------------------------------------
__device__ float  g_q [BSZ * SEQ * NH  * HD];
__device__ float  g_k [BSZ * SEQ * NKV * HD];
__device__ float  g_v [BSZ * SEQ * NKV * HD];
__device__ __half g_qe[(size_t)BSZ * NH  * SEQ * DQK];
__device__ __half g_ke[(size_t)BSZ * NH  * SEQ * DQK];
__device__ __half g_vt[(size_t)BSZ * NKV * HD * SEQ];   // [b][kvh][d][T]
__device__ __half g_yh[BSZ * SEQ * NH * HD];
__device__ __half g_xh [BSZ * SEQ * DM];
__device__ __half g_wq [NH  * HD * DM];
__device__ __half g_wk [NKV * HD * DM];
__device__ __half g_wv [NKV * HD * DM];
__device__ __half g_wo [DM * NH * HD];
// phase tables
__device__ float g_cs [SEQ * HD];
__device__ float g_sn [SEQ * HD];
__device__ float g_cd [NH * HD];
__device__ float g_sd [NH * HD];

#define MMA_F16(d, a, b)                                                      \
    asm volatile(                                                             \
        "mma.sync.aligned.m16n8k16.row.col.f32.f16.f16.f32 "                  \
        "{%0,%1,%2,%3},{%4,%5,%6,%7},{%8,%9},{%0,%1,%2,%3};\n"                \
        : "+f"((d)[0]), "+f"((d)[1]), "+f"((d)[2]), "+f"((d)[3])              \
        : "r"((a)[0]), "r"((a)[1]), "r"((a)[2]), "r"((a)[3]),                 \
          "r"((b)[0]), "r"((b)[1]))

#define LDSM_X4(r0, r1, r2, r3, addr)                                         \
    asm volatile("ldmatrix.sync.aligned.m8n8.x4.shared.b16 "                  \
                 "{%0,%1,%2,%3}, [%4];"                                       \
                 : "=r"(r0), "=r"(r1), "=r"(r2), "=r"(r3) : "r"(addr))

// ---------------------------------------------------------------------------
// Prep kernels
// ---------------------------------------------------------------------------
__global__ void f2h_kernel(const float* __restrict__ in,
                           __half* __restrict__ out, int n)
{
    int i = (blockIdx.x * blockDim.x + threadIdx.x) * 4;
    if (i < n) {
        float4 v = *(const float4*)(in + i);
        __half2 h0 = __floats2half2_rn(v.x, v.y);
        __half2 h1 = __floats2half2_rn(v.z, v.w);
        uint2 u;
        u.x = *(uint32_t*)&h0;
        u.y = *(uint32_t*)&h1;
        *(uint2*)(out + i) = u;
    }
}

__global__ void transpose_h_kernel(const float* __restrict__ in,
                                   __half* __restrict__ out, int K, int N)
{
    __shared__ float tile[32][33];
    const int n0 = blockIdx.x * 32;
    const int k0 = blockIdx.y * 32;
    const int tx = threadIdx.x;
    const int ty = threadIdx.y;   // block (32, 8)
    #pragma unroll
    for (int j = 0; j < 32; j += 8)
        tile[ty + j][tx] = in[(size_t)(k0 + ty + j) * N + n0 + tx];
    __syncthreads();
    #pragma unroll
    for (int j = 0; j < 32; j += 8)
        out[(size_t)(n0 + ty + j) * K + k0 + tx] = __float2half(tile[tx][ty + j]);
}

__global__ void vtrans_kernel(const float* __restrict__ v,
                              __half* __restrict__ vt)
{
    __shared__ float tile[32][33];
    const int t0 = blockIdx.x * 32;
    const int d0 = blockIdx.y * 32;
    const int z  = blockIdx.z;
    const int b  = z / NKV;
    const int kh = z % NKV;
    const int tx = threadIdx.x;
    const int ty = threadIdx.y;   // block (32, 8)
    #pragma unroll
    for (int j = 0; j < 32; j += 8)
        tile[ty + j][tx] =
            v[((size_t)(b * SEQ + t0 + ty + j)) * (NKV * HD) + kh * HD + d0 + tx];
    __syncthreads();
    #pragma unroll
    for (int j = 0; j < 32; j += 8)
        vt[((size_t)(b * NKV + kh) * HD + d0 + ty + j) * SEQ + t0 + tx] =
            __float2half(tile[tx][ty + j]);
}

__global__ void angles_kernel(float* __restrict__ cs, float* __restrict__ sn)
{
    const int i = blockIdx.x * blockDim.x + threadIdx.x;
    if (i >= SEQ * HD) return;
    const int d = i & (HD - 1);
    const int t = i >> 7;
    const double TWO_PI  = 6.283185307179586;
    const double INV_2PI = 0.15915494309189535;
    const double f   = exp(-9.210340371976184 * (double)d / 128.0);
    const double ang = (double)t * f;
    const double ar  = ang - floor(ang * INV_2PI) * TWO_PI;
    float sa, ca;
    sincosf((float)ar, &sa, &ca);
    cs[i] = ca;
    sn[i] = sa;
}

__global__ void delta_kernel(const float* __restrict__ delta,
                             float* __restrict__ cd, float* __restrict__ sd)
{
    const int i = blockIdx.x * blockDim.x + threadIdx.x;
    if (i >= NH * HD) return;
    float dl = delta[i];
    dl = fminf(fmaxf(dl, -6.2831855f), 0.0f);
    float s, c;
    sincosf(dl, &s, &c);
    cd[i] = c;
    sd[i] = s;
}

__device__ __forceinline__ float softplus_fast(float x)
{
    if (x > 15.0f) return x;
    return __logf(1.0f + __expf(x));
}

__global__ void encode_kernel(const float* __restrict__ q,
                              const float* __restrict__ k,
                              const float* __restrict__ cs,
                              const float* __restrict__ sn,
                              const float* __restrict__ cd,
                              const float* __restrict__ sd,
                              __half* __restrict__ qe,
                              __half* __restrict__ ke)
{
    const int i = blockIdx.x * blockDim.x + threadIdx.x;
    const int total = BSZ * NH * SEQ * HD;
    if (i >= total) return;

    const int d = i & (HD - 1);
    const int t = (i >> 7) & (SEQ - 1);
    const int h = (i >> 18) & (NH - 1);
    const int b = i >> 22;

    const float ca = cs[(t << 7) + d];
    const float sa = sn[(t << 7) + d];

    {
        float qv  = q[((size_t)(b * SEQ + t)) * (NH * HD) + h * HD + d];
        float mag = softplus_fast(qv);
        size_t o = (((size_t)(b * NH + h)) * SEQ + t) * DQK + d;
        qe[o]      = __float2half(mag * ca);
        qe[o + HD] = __float2half(mag * sa);
    }

    {
        const float c = cd[(h << 7) + d];
        const float s = sd[(h << 7) + d];
        const float ck = ca * c - sa * s;
        const float sk = sa * c + ca * s;
        float kv  = k[((size_t)(b * SEQ + t)) * (NKV * HD) + (h >> 1) * HD + d];
        float mag = softplus_fast(kv);
        size_t o = (((size_t)(b * NH + h)) * SEQ + t) * DQK + d;
        ke[o]      = __float2half(mag * ck);
        ke[o + HD] = __float2half(mag * sk);
    }
}

// ---------------------------------------------------------------------------
// fp16 GEMM: 128x128x32 tile, 128 threads (4 warps, warp tile 64x64),
// ldmatrix fragment loads, 3-stage cp.async.
// ---------------------------------------------------------------------------
#define GASTR 40
#define G_STG_H (2 * 128 * GASTR)
#define G_STAGES 3
#define GEMM_SMEM_BYTES (G_STAGES * G_STG_H * 2)

__global__ void __launch_bounds__(128)
gemm_h_kernel(const __half* __restrict__ A,
              const __half* __restrict__ B0, float* __restrict__ C0,
              const __half* __restrict__ B1, float* __restrict__ C1,
              int M, int N, int K)
{
    extern __shared__ __half smh[];

    const __half* B = blockIdx.z ? B1 : B0;
    float*        C = blockIdx.z ? C1 : C0;

    const int tid    = threadIdx.x;
    const int wid    = tid >> 5;
    const int lane   = tid & 31;
    const int g      = lane >> 2;
    const int t      = lane & 3;
    const int lane15 = lane & 15;
    const int lanehi = (lane >> 4) * 8;

    const int mbase = (wid & 1) * 64;
    const int nbase = (wid >> 1) * 64;

    const __half* Ag = A + (size_t)blockIdx.y * 128 * K;
    const __half* Bg = B + (size_t)blockIdx.x * 128 * K;

    const uint32_t smb   = (uint32_t)__cvta_generic_to_shared(smh);
    const uint32_t a_off = (uint32_t)((mbase + lane15) * GASTR + lanehi);
    const uint32_t b_off = (uint32_t)((nbase + lane15) * GASTR + lanehi);

    float acc[4][8][4];
    #pragma unroll
    for (int i = 0; i < 4; i++)
        #pragma unroll
        for (int j = 0; j < 8; j++)
            #pragma unroll
            for (int u = 0; u < 4; u++) acc[i][j][u] = 0.0f;

    const int kiters = K / 32;

    auto issue_stage = [&](int s, int it) {
        const int k0 = it * 32;
        unsigned sa = smb + (unsigned)s * (G_STG_H * 2u);
        unsigned sb = sa + 128u * GASTR * 2u;
        #pragma unroll
        for (int j = 0; j < 4; j++) {
            int c = tid + j * 128;              // 0..511
            int r  = c >> 2;                    // 0..127
            int ch = (c & 3) * 8;
            const __half* srca = Ag + (size_t)r * K + k0 + ch;
            asm volatile("cp.async.cg.shared.global [%0], [%1], 16;\n"
                         :: "r"(sa + (unsigned)(r * GASTR + ch) * 2u), "l"(srca));
            const __half* srcb = Bg + (size_t)r * K + k0 + ch;
            asm volatile("cp.async.cg.shared.global [%0], [%1], 16;\n"
                         :: "r"(sb + (unsigned)(r * GASTR + ch) * 2u), "l"(srcb));
        }
        asm volatile("cp.async.commit_group;\n");
    };

    issue_stage(0, 0);
    issue_stage(1, 1);

    for (int it = 0; it < kiters; it++) {
        if (it + 2 < kiters)
            issue_stage((it + 2) % G_STAGES, it + 2);
        else
            asm volatile("cp.async.commit_group;\n");
        asm volatile("cp.async.wait_group 2;\n");
        __syncthreads();

        const uint32_t sa = smb + (uint32_t)(it % G_STAGES) * (G_STG_H * 2u);
        const uint32_t sb = sa + 128u * GASTR * 2u;

        #pragma unroll
        for (int ks = 0; ks < 2; ks++) {
            const int kk = ks * 16;
            uint32_t af[4][4];
            #pragma unroll
            for (int mt = 0; mt < 4; mt++)
                LDSM_X4(af[mt][0], af[mt][1], af[mt][2], af[mt][3],
                        sa + (a_off + mt * 16 * GASTR + kk) * 2u);
            uint32_t bf[8][2];
            #pragma unroll
            for (int p = 0; p < 4; p++) {
                uint32_t r0, r1, r2, r3;
                LDSM_X4(r0, r1, r2, r3,
                        sb + (b_off + p * 16 * GASTR + kk) * 2u);
                bf[2 * p][0]     = r0;
                bf[2 * p + 1][0] = r1;
                bf[2 * p][1]     = r2;
                bf[2 * p + 1][1] = r3;
            }
            #pragma unroll
            for (int mt = 0; mt < 4; mt++)
                #pragma unroll
                for (int nt = 0; nt < 8; nt++)
                    MMA_F16(acc[mt][nt], af[mt], bf[nt]);
        }
        __syncthreads();
    }

    #pragma unroll
    for (int mt = 0; mt < 4; mt++) {
        #pragma unroll
        for (int nt = 0; nt < 8; nt++) {
            int row = blockIdx.y * 128 + mbase + mt * 16 + g;
            int col = blockIdx.x * 128 + nbase + nt * 8 + 2 * t;
            *(float2*)(C + (size_t)row * N + col) =
                make_float2(acc[mt][nt][0], acc[mt][nt][1]);
            *(float2*)(C + (size_t)(row + 8) * N + col) =
                make_float2(acc[mt][nt][2], acc[mt][nt][3]);
        }
    }
}

// ---------------------------------------------------------------------------
// fp16 causal flash attention. BM=64, BN=64, 128 threads (4 warps x 16 rows).
// QK k=256, PV k=64. V pre-transposed [d][T]. Double-buffered cp.async.
// ---------------------------------------------------------------------------
#define FBM 64
#define FBN 64
#define QSTR 264
#define KSTR 264
#define VSTR 72
#define PSTR 72

#define FL_Q_H (FBM * QSTR)
#define FL_K_H (2 * FBN * KSTR)
#define FL_V_H (2 * HD * VSTR)
#define FL_P_H (FBM * PSTR)
#define FLASH_SMEM_BYTES ((FL_Q_H + FL_K_H + FL_V_H + FL_P_H) * 2)

__global__ void __launch_bounds__(128)
flash_h_kernel(const __half* __restrict__ Qe, const __half* __restrict__ Ke,
               const __half* __restrict__ Vt, __half* __restrict__ Y)
{
    extern __shared__ __half smh[];
    __half* Ps = smh + FL_Q_H + FL_K_H + FL_V_H;

    const int qt = blockIdx.x;
    const int h  = blockIdx.y;
    const int b  = blockIdx.z;
    const int q0 = qt * FBM;

    const int tid    = threadIdx.x;
    const int wid    = tid >> 5;
    const int lane   = tid & 31;
    const int g      = lane >> 2;
    const int t      = lane & 3;
    const int lane15 = lane & 15;
    const int lanehi = (lane >> 4) * 8;
    const int r0     = wid * 16;

    const __half* qbase = Qe + (((size_t)(b * NH + h)) * SEQ + q0) * DQK;
    const __half* kbase = Ke + (((size_t)(b * NH + h)) * SEQ) * DQK;
    const __half* vbase = Vt + ((size_t)(b * NKV + (h >> 1)) * HD) * SEQ;

    const uint32_t smb  = (uint32_t)__cvta_generic_to_shared(smh);
    const uint32_t qs_b = smb;
    const uint32_t ks_b = smb + FL_Q_H * 2u;
    const uint32_t vs_b = smb + (FL_Q_H + FL_K_H) * 2u;
    const uint32_t ps_b = smb + (FL_Q_H + FL_K_H + FL_V_H) * 2u;

    const uint32_t q_off = (uint32_t)((r0 + lane15) * QSTR + lanehi);
    const uint32_t k_off = (uint32_t)(lane15 * KSTR + lanehi);
    const uint32_t v_off = (uint32_t)(lane15 * VSTR + lanehi);
    const uint32_t p_off = (uint32_t)((r0 + lane15) * PSTR + lanehi);

    // Q tile 64x256 halves = 2048 chunks
    {
        #pragma unroll
        for (int l = 0; l < 16; l++) {
            int i = l * 128 + tid;
            int r  = i >> 5;
            int c8 = (i & 31) * 8;
            const __half* src = qbase + (size_t)r * DQK + c8;
            asm volatile("cp.async.cg.shared.global [%0], [%1], 16;\n"
                         :: "r"(qs_b + (unsigned)(r * QSTR + c8) * 2u), "l"(src));
        }
        asm volatile("cp.async.commit_group;\n");
    }

    auto issue_kv = [&](int s, int kt) {
        const int k0 = kt * FBN;
        unsigned ks = ks_b + (unsigned)s * (FBN * KSTR * 2u);
        unsigned vs = vs_b + (unsigned)s * (HD * VSTR * 2u);
        #pragma unroll
        for (int l = 0; l < 16; l++) {      // K: 64x256 halves = 2048 chunks
            int i = l * 128 + tid;
            int r  = i >> 5;
            int c8 = (i & 31) * 8;
            const __half* src = kbase + (size_t)(k0 + r) * DQK + c8;
            asm volatile("cp.async.cg.shared.global [%0], [%1], 16;\n"
                         :: "r"(ks + (unsigned)(r * KSTR + c8) * 2u), "l"(src));
        }
        #pragma unroll
        for (int l = 0; l < 8; l++) {       // V: 128 d x 64 t halves = 1024 chunks
            int i = l * 128 + tid;
            int rd = i >> 3;                // 0..127
            int c8 = (i & 7) * 8;           // 0..56
            const __half* src = vbase + (size_t)rd * SEQ + k0 + c8;
            asm volatile("cp.async.cg.shared.global [%0], [%1], 16;\n"
                         :: "r"(vs + (unsigned)(rd * VSTR + c8) * 2u), "l"(src));
        }
        asm volatile("cp.async.commit_group;\n");
    };

    float m[2]    = { -3.0e38f, -3.0e38f };
    float lsum[2] = { 0.0f, 0.0f };
    float oacc[16][4];
    #pragma unroll
    for (int j = 0; j < 16; j++)
        #pragma unroll
        for (int u = 0; u < 4; u++) oacc[j][u] = 0.0f;

    const float scale = 0.08838834764831845f;
    const int ntl = qt + 1;

    issue_kv(0, 0);

    for (int kt = 0; kt < ntl; kt++) {
        const int k0 = kt * FBN;
        if (kt + 1 < ntl)
            issue_kv((kt + 1) & 1, kt + 1);
        else
            asm volatile("cp.async.commit_group;\n");
        asm volatile("cp.async.wait_group 1;\n");
        __syncthreads();

        const uint32_t ksb = ks_b + (uint32_t)(kt & 1) * (FBN * KSTR * 2u);
        const uint32_t vsb = vs_b + (uint32_t)(kt & 1) * (HD * VSTR * 2u);

        // ---- S = Q K^T (16x64 per warp, k=256) ----
        float sacc[8][4];
        #pragma unroll
        for (int j = 0; j < 8; j++)
            #pragma unroll
            for (int u = 0; u < 4; u++) sacc[j][u] = 0.0f;

        #pragma unroll
        for (int ks = 0; ks < 16; ks++) {
            const int kk = ks * 16;
            uint32_t a[4];
            LDSM_X4(a[0], a[1], a[2], a[3], qs_b + (q_off + kk) * 2u);
            uint32_t bf[8][2];
            #pragma unroll
            for (int p = 0; p < 4; p++) {
                uint32_t r0r, r1r, r2r, r3r;
                LDSM_X4(r0r, r1r, r2r, r3r,
                        ksb + (k_off + p * 16 * KSTR + kk) * 2u);
                bf[2 * p][0]     = r0r;
                bf[2 * p + 1][0] = r1r;
                bf[2 * p][1]     = r2r;
                bf[2 * p + 1][1] = r3r;
            }
            #pragma unroll
            for (int j = 0; j < 8; j++)
                MMA_F16(sacc[j], a, bf[j]);
        }

        // ---- online softmax (rows g, g+8; warp-local) ----
        const bool diag = (kt == qt);
        #pragma unroll
        for (int half = 0; half < 2; half++) {
            const int row = q0 + r0 + g + 8 * half;
            float v[16];
            float mloc = -3.0e38f;
            #pragma unroll
            for (int j = 0; j < 8; j++) {
                #pragma unroll
                for (int c = 0; c < 2; c++) {
                    int col = k0 + 8 * j + 2 * t + c;
                    float sv = sacc[j][2 * half + c] * scale;
                    if (diag && col > row) sv = -3.0e38f;
                    v[2 * j + c] = sv;
                    mloc = fmaxf(mloc, sv);
                }
            }
            mloc = fmaxf(mloc, __shfl_xor_sync(0xffffffffu, mloc, 1));
            mloc = fmaxf(mloc, __shfl_xor_sync(0xffffffffu, mloc, 2));
            float mn = fmaxf(m[half], mloc);
            float alpha = __expf(m[half] - mn);
            float rs = 0.0f;
            __half2 ph[8];
            #pragma unroll
            for (int j = 0; j < 8; j++) {
                float p0 = __expf(v[2 * j]     - mn);
                float p1 = __expf(v[2 * j + 1] - mn);
                __half2 h2 = __floats2half2_rn(p0, p1);
                ph[j] = h2;
                float2 pr = __half22float2(h2);
                rs += pr.x + pr.y;
            }
            rs += __shfl_xor_sync(0xffffffffu, rs, 1);
            rs += __shfl_xor_sync(0xffffffffu, rs, 2);
            lsum[half] = lsum[half] * alpha + rs;
            m[half] = mn;
            #pragma unroll
            for (int j = 0; j < 16; j++) {
                oacc[j][2 * half]     *= alpha;
                oacc[j][2 * half + 1] *= alpha;
            }
            #pragma unroll
            for (int j = 0; j < 8; j++)
                *(__half2*)(Ps + (size_t)(r0 + g + 8 * half) * PSTR
                            + 8 * j + 2 * t) = ph[j];
        }
        __syncwarp();

        // ---- O += P V (16x128 per warp, k=64) ----
        #pragma unroll
        for (int ks = 0; ks < 4; ks++) {
            const int kk = ks * 16;
            uint32_t a[4];
            LDSM_X4(a[0], a[1], a[2], a[3], ps_b + (p_off + kk) * 2u);
            #pragma unroll
            for (int p = 0; p < 8; p++) {
                uint32_t r0r, r1r, r2r, r3r;
                LDSM_X4(r0r, r1r, r2r, r3r,
                        vsb + (v_off + p * 16 * VSTR + kk) * 2u);
                uint32_t b0[2] = { r0r, r2r };
                uint32_t b1[2] = { r1r, r3r };
                MMA_F16(oacc[2 * p],     a, b0);
                MMA_F16(oacc[2 * p + 1], a, b1);
            }
        }
        __syncthreads();
    }

    // epilogue
    #pragma unroll
    for (int half = 0; half < 2; half++) {
        const int row = q0 + r0 + g + 8 * half;
        const float inv = 1.0f / lsum[half];
        __half* yr = Y + ((size_t)b * SEQ + row) * DM + h * HD;
        #pragma unroll
        for (int j = 0; j < 16; j++)
            *(__half2*)(yr + 8 * j + 2 * t) =
                __floats2half2_rn(oacc[j][2 * half] * inv,
                                  oacc[j][2 * half + 1] * inv);
    }
}

// ---------------------------------------------------------------------------
// Launch
// ---------------------------------------------------------------------------
extern "C" void kernel_launch(void* const* d_in, const int* in_sizes, int n_in,
                              void* d_out, int out_size)
{
    const float* x     = (const float*)d_in[0];
    const float* Wq    = (const float*)d_in[1];
    const float* Wk    = (const float*)d_in[2];
    const float* Wv    = (const float*)d_in[3];
    const float* Wo    = (const float*)d_in[4];
    const float* delta = (const float*)d_in[5];
    float* out = (float*)d_out;

    float  *q_, *k_, *v_, *cs_, *sn_, *cd_, *sd_;
    __half *qe_, *ke_, *vt_, *yh_, *xh_, *wq_, *wk_, *wv_, *wo_;
    cudaGetSymbolAddress((void**)&q_,  g_q);
    cudaGetSymbolAddress((void**)&k_,  g_k);
    cudaGetSymbolAddress((void**)&v_,  g_v);
    cudaGetSymbolAddress((void**)&qe_, g_qe);
    cudaGetSymbolAddress((void**)&ke_, g_ke);
    cudaGetSymbolAddress((void**)&vt_, g_vt);
    cudaGetSymbolAddress((void**)&yh_, g_yh);
    cudaGetSymbolAddress((void**)&xh_, g_xh);
    cudaGetSymbolAddress((void**)&wq_, g_wq);
    cudaGetSymbolAddress((void**)&wk_, g_wk);
    cudaGetSymbolAddress((void**)&wv_, g_wv);
    cudaGetSymbolAddress((void**)&wo_, g_wo);
    cudaGetSymbolAddress((void**)&cs_, g_cs);
    cudaGetSymbolAddress((void**)&sn_, g_sn);
    cudaGetSymbolAddress((void**)&cd_, g_cd);
    cudaGetSymbolAddress((void**)&sd_, g_sd);

    const int M = BSZ * SEQ;   // 4096

    cudaFuncSetAttribute(gemm_h_kernel,
                         cudaFuncAttributeMaxDynamicSharedMemorySize,
                         GEMM_SMEM_BYTES);
    cudaFuncSetAttribute(flash_h_kernel,
                         cudaFuncAttributeMaxDynamicSharedMemorySize,
                         FLASH_SMEM_BYTES);

    // prep
    {
        int n = BSZ * SEQ * DM;
        f2h_kernel<<<(n / 4 + 255) / 256, 256>>>(x, xh_, n);
        dim3 blk(32, 8);
        transpose_h_kernel<<<dim3(DM / 32,       DM / 32), blk>>>(Wq, wq_, DM, DM);
        transpose_h_kernel<<<dim3(NKV * HD / 32, DM / 32), blk>>>(Wk, wk_, DM, NKV * HD);
        transpose_h_kernel<<<dim3(NKV * HD / 32, DM / 32), blk>>>(Wv, wv_, DM, NKV * HD);
        transpose_h_kernel<<<dim3(DM / 32,       DM / 32), blk>>>(Wo, wo_, DM, DM);
        angles_kernel<<<(SEQ * HD + 255) / 256, 256>>>(cs_, sn_);
        delta_kernel<<<(NH * HD + 255) / 256, 256>>>(delta, cd_, sd_);
    }

    // projections
    gemm_h_kernel<<<dim3(DM / 128, M / 128, 1), 128, GEMM_SMEM_BYTES>>>(
        xh_, wq_, q_, wq_, q_, M, DM, DM);
    gemm_h_kernel<<<dim3(NKV * HD / 128, M / 128, 2), 128, GEMM_SMEM_BYTES>>>(
        xh_, wk_, k_, wv_, v_, M, NKV * HD, DM);

    // encode + V transpose
    {
        const int total = BSZ * NH * SEQ * HD;
        encode_kernel<<<(total + 255) / 256, 256>>>(q_, k_, cs_, sn_, cd_, sd_,
                                                    qe_, ke_);
        vtrans_kernel<<<dim3(SEQ / 32, HD / 32, BSZ * NKV), dim3(32, 8)>>>(v_, vt_);
    }

    // flash attention
    flash_h_kernel<<<dim3(SEQ / FBM, NH, BSZ), 128, FLASH_SMEM_BYTES>>>(
        qe_, ke_, vt_, yh_);

    // output projection
    gemm_h_kernel<<<dim3(DM / 128, M / 128, 1), 128, GEMM_SMEM_BYTES>>>(
        yh_, wo_, out, wo_, out, M, DM, DM);
}

// round 12
// speedup vs baseline: 5.7250x; 1.0001x over previous
#include <cuda_runtime.h>
#include <cuda_fp16.h>
#include <math.h>
#include <stdint.h>

// Problem constants
#define BSZ   2
#define SEQ   2048
#define DM    2048
#define NH    16
#define NKV   8
#define HD    128
#define DQK   256

// ---------------------------------------------------------------------------
// Scratch
// ---------------------------------------------------------------------------
__device__ float  g_q [BSZ * SEQ * NH  * HD];
__device__ float  g_k [BSZ * SEQ * NKV * HD];
__device__ float  g_v [BSZ * SEQ * NKV * HD];
__device__ __half g_qe[(size_t)BSZ * NH  * SEQ * DQK];
__device__ __half g_ke[(size_t)BSZ * NH  * SEQ * DQK];
__device__ __half g_vt[(size_t)BSZ * NKV * HD * SEQ];   // [b][kvh][d][T]
__device__ __half g_yh[BSZ * SEQ * NH * HD];
__device__ __half g_xh [BSZ * SEQ * DM];
__device__ __half g_wq [NH  * HD * DM];
__device__ __half g_wk [NKV * HD * DM];
__device__ __half g_wv [NKV * HD * DM];
__device__ __half g_wo [DM * NH * HD];
// phase tables
__device__ float g_cs [SEQ * HD];
__device__ float g_sn [SEQ * HD];
__device__ float g_cd [NH * HD];
__device__ float g_sd [NH * HD];

#define MMA_F16(d, a, b)                                                      \
    asm volatile(                                                             \
        "mma.sync.aligned.m16n8k16.row.col.f32.f16.f16.f32 "                  \
        "{%0,%1,%2,%3},{%4,%5,%6,%7},{%8,%9},{%0,%1,%2,%3};\n"                \
        : "+f"((d)[0]), "+f"((d)[1]), "+f"((d)[2]), "+f"((d)[3])              \
        : "r"((a)[0]), "r"((a)[1]), "r"((a)[2]), "r"((a)[3]),                 \
          "r"((b)[0]), "r"((b)[1]))

#define LDSM_X4(r0, r1, r2, r3, addr)                                         \
    asm volatile("ldmatrix.sync.aligned.m8n8.x4.shared.b16 "                  \
                 "{%0,%1,%2,%3}, [%4];"                                       \
                 : "=r"(r0), "=r"(r1), "=r"(r2), "=r"(r3) : "r"(addr))

// ---------------------------------------------------------------------------
// Prep kernels
// ---------------------------------------------------------------------------
__global__ void f2h_kernel(const float* __restrict__ in,
                           __half* __restrict__ out, int n)
{
    int i = (blockIdx.x * blockDim.x + threadIdx.x) * 4;
    if (i < n) {
        float4 v = *(const float4*)(in + i);
        __half2 h0 = __floats2half2_rn(v.x, v.y);
        __half2 h1 = __floats2half2_rn(v.z, v.w);
        uint2 u;
        u.x = *(uint32_t*)&h0;
        u.y = *(uint32_t*)&h1;
        *(uint2*)(out + i) = u;
    }
}

__global__ void transpose_h_kernel(const float* __restrict__ in,
                                   __half* __restrict__ out, int K, int N)
{
    __shared__ float tile[32][33];
    const int n0 = blockIdx.x * 32;
    const int k0 = blockIdx.y * 32;
    const int tx = threadIdx.x;
    const int ty = threadIdx.y;   // block (32, 8)
    #pragma unroll
    for (int j = 0; j < 32; j += 8)
        tile[ty + j][tx] = in[(size_t)(k0 + ty + j) * N + n0 + tx];
    __syncthreads();
    #pragma unroll
    for (int j = 0; j < 32; j += 8)
        out[(size_t)(n0 + ty + j) * K + k0 + tx] = __float2half(tile[tx][ty + j]);
}

__global__ void vtrans_kernel(const float* __restrict__ v,
                              __half* __restrict__ vt)
{
    __shared__ float tile[32][33];
    const int t0 = blockIdx.x * 32;
    const int d0 = blockIdx.y * 32;
    const int z  = blockIdx.z;
    const int b  = z / NKV;
    const int kh = z % NKV;
    const int tx = threadIdx.x;
    const int ty = threadIdx.y;   // block (32, 8)
    #pragma unroll
    for (int j = 0; j < 32; j += 8)
        tile[ty + j][tx] =
            v[((size_t)(b * SEQ + t0 + ty + j)) * (NKV * HD) + kh * HD + d0 + tx];
    __syncthreads();
    #pragma unroll
    for (int j = 0; j < 32; j += 8)
        vt[((size_t)(b * NKV + kh) * HD + d0 + ty + j) * SEQ + t0 + tx] =
            __float2half(tile[tx][ty + j]);
}

__global__ void angles_kernel(float* __restrict__ cs, float* __restrict__ sn)
{
    const int i = blockIdx.x * blockDim.x + threadIdx.x;
    if (i >= SEQ * HD) return;
    const int d = i & (HD - 1);
    const int t = i >> 7;
    const double TWO_PI  = 6.283185307179586;
    const double INV_2PI = 0.15915494309189535;
    const double f   = exp(-9.210340371976184 * (double)d / 128.0);
    const double ang = (double)t * f;
    const double ar  = ang - floor(ang * INV_2PI) * TWO_PI;
    float sa, ca;
    sincosf((float)ar, &sa, &ca);
    cs[i] = ca;
    sn[i] = sa;
}

__global__ void delta_kernel(const float* __restrict__ delta,
                             float* __restrict__ cd, float* __restrict__ sd)
{
    const int i = blockIdx.x * blockDim.x + threadIdx.x;
    if (i >= NH * HD) return;
    float dl = delta[i];
    dl = fminf(fmaxf(dl, -6.2831855f), 0.0f);
    float s, c;
    sincosf(dl, &s, &c);
    cd[i] = c;
    sd[i] = s;
}

__device__ __forceinline__ float softplus_fast(float x)
{
    if (x > 15.0f) return x;
    return __logf(1.0f + __expf(x));
}

__global__ void encode_kernel(const float* __restrict__ q,
                              const float* __restrict__ k,
                              const float* __restrict__ cs,
                              const float* __restrict__ sn,
                              const float* __restrict__ cd,
                              const float* __restrict__ sd,
                              __half* __restrict__ qe,
                              __half* __restrict__ ke)
{
    const int i = blockIdx.x * blockDim.x + threadIdx.x;
    const int total = BSZ * NH * SEQ * HD;
    if (i >= total) return;

    const int d = i & (HD - 1);
    const int t = (i >> 7) & (SEQ - 1);
    const int h = (i >> 18) & (NH - 1);
    const int b = i >> 22;

    const float ca = cs[(t << 7) + d];
    const float sa = sn[(t << 7) + d];

    {
        float qv  = q[((size_t)(b * SEQ + t)) * (NH * HD) + h * HD + d];
        float mag = softplus_fast(qv);
        size_t o = (((size_t)(b * NH + h)) * SEQ + t) * DQK + d;
        qe[o]      = __float2half(mag * ca);
        qe[o + HD] = __float2half(mag * sa);
    }

    {
        const float c = cd[(h << 7) + d];
        const float s = sd[(h << 7) + d];
        const float ck = ca * c - sa * s;
        const float sk = sa * c + ca * s;
        float kv  = k[((size_t)(b * SEQ + t)) * (NKV * HD) + (h >> 1) * HD + d];
        float mag = softplus_fast(kv);
        size_t o = (((size_t)(b * NH + h)) * SEQ + t) * DQK + d;
        ke[o]      = __float2half(mag * ck);
        ke[o + HD] = __float2half(mag * sk);
    }
}

// ---------------------------------------------------------------------------
// fp16 GEMM: 128x128x32 tile, 128 threads (4 warps, warp tile 64x64),
// ldmatrix fragment loads, 3-stage cp.async.  (unchanged from R11)
// ---------------------------------------------------------------------------
#define GASTR 40
#define G_STG_H (2 * 128 * GASTR)
#define G_STAGES 3
#define GEMM_SMEM_BYTES (G_STAGES * G_STG_H * 2)

__global__ void __launch_bounds__(128)
gemm_h_kernel(const __half* __restrict__ A,
              const __half* __restrict__ B0, float* __restrict__ C0,
              const __half* __restrict__ B1, float* __restrict__ C1,
              int M, int N, int K)
{
    extern __shared__ __half smh[];

    const __half* B = blockIdx.z ? B1 : B0;
    float*        C = blockIdx.z ? C1 : C0;

    const int tid    = threadIdx.x;
    const int wid    = tid >> 5;
    const int lane   = tid & 31;
    const int g      = lane >> 2;
    const int t      = lane & 3;
    const int lane15 = lane & 15;
    const int lanehi = (lane >> 4) * 8;

    const int mbase = (wid & 1) * 64;
    const int nbase = (wid >> 1) * 64;

    const __half* Ag = A + (size_t)blockIdx.y * 128 * K;
    const __half* Bg = B + (size_t)blockIdx.x * 128 * K;

    const uint32_t smb   = (uint32_t)__cvta_generic_to_shared(smh);
    const uint32_t a_off = (uint32_t)((mbase + lane15) * GASTR + lanehi);
    const uint32_t b_off = (uint32_t)((nbase + lane15) * GASTR + lanehi);

    float acc[4][8][4];
    #pragma unroll
    for (int i = 0; i < 4; i++)
        #pragma unroll
        for (int j = 0; j < 8; j++)
            #pragma unroll
            for (int u = 0; u < 4; u++) acc[i][j][u] = 0.0f;

    const int kiters = K / 32;

    auto issue_stage = [&](int s, int it) {
        const int k0 = it * 32;
        unsigned sa = smb + (unsigned)s * (G_STG_H * 2u);
        unsigned sb = sa + 128u * GASTR * 2u;
        #pragma unroll
        for (int j = 0; j < 4; j++) {
            int c = tid + j * 128;              // 0..511
            int r  = c >> 2;                    // 0..127
            int ch = (c & 3) * 8;
            const __half* srca = Ag + (size_t)r * K + k0 + ch;
            asm volatile("cp.async.cg.shared.global [%0], [%1], 16;\n"
                         :: "r"(sa + (unsigned)(r * GASTR + ch) * 2u), "l"(srca));
            const __half* srcb = Bg + (size_t)r * K + k0 + ch;
            asm volatile("cp.async.cg.shared.global [%0], [%1], 16;\n"
                         :: "r"(sb + (unsigned)(r * GASTR + ch) * 2u), "l"(srcb));
        }
        asm volatile("cp.async.commit_group;\n");
    };

    issue_stage(0, 0);
    issue_stage(1, 1);

    for (int it = 0; it < kiters; it++) {
        if (it + 2 < kiters)
            issue_stage((it + 2) % G_STAGES, it + 2);
        else
            asm volatile("cp.async.commit_group;\n");
        asm volatile("cp.async.wait_group 2;\n");
        __syncthreads();

        const uint32_t sa = smb + (uint32_t)(it % G_STAGES) * (G_STG_H * 2u);
        const uint32_t sb = sa + 128u * GASTR * 2u;

        #pragma unroll
        for (int ks = 0; ks < 2; ks++) {
            const int kk = ks * 16;
            uint32_t af[4][4];
            #pragma unroll
            for (int mt = 0; mt < 4; mt++)
                LDSM_X4(af[mt][0], af[mt][1], af[mt][2], af[mt][3],
                        sa + (a_off + mt * 16 * GASTR + kk) * 2u);
            uint32_t bf[8][2];
            #pragma unroll
            for (int p = 0; p < 4; p++) {
                uint32_t r0, r1, r2, r3;
                LDSM_X4(r0, r1, r2, r3,
                        sb + (b_off + p * 16 * GASTR + kk) * 2u);
                bf[2 * p][0]     = r0;
                bf[2 * p + 1][0] = r1;
                bf[2 * p][1]     = r2;
                bf[2 * p + 1][1] = r3;
            }
            #pragma unroll
            for (int mt = 0; mt < 4; mt++)
                #pragma unroll
                for (int nt = 0; nt < 8; nt++)
                    MMA_F16(acc[mt][nt], af[mt], bf[nt]);
        }
        __syncthreads();
    }

    #pragma unroll
    for (int mt = 0; mt < 4; mt++) {
        #pragma unroll
        for (int nt = 0; nt < 8; nt++) {
            int row = blockIdx.y * 128 + mbase + mt * 16 + g;
            int col = blockIdx.x * 128 + nbase + nt * 8 + 2 * t;
            *(float2*)(C + (size_t)row * N + col) =
                make_float2(acc[mt][nt][0], acc[mt][nt][1]);
            *(float2*)(C + (size_t)(row + 8) * N + col) =
                make_float2(acc[mt][nt][2], acc[mt][nt][3]);
        }
    }
}

// ---------------------------------------------------------------------------
// fp16 causal flash attention. BM=128, BN=64, 256 threads (8 warps x 16 rows).
// QK k=256, PV k=64. V pre-transposed [d][T]. Double-buffered cp.async.
// ---------------------------------------------------------------------------
#define FBM 128
#define FBN 64
#define QSTR 264
#define KSTR 264
#define VSTR 72
#define PSTR 72

#define FL_Q_H (FBM * QSTR)
#define FL_K_H (2 * FBN * KSTR)
#define FL_V_H (2 * HD * VSTR)
#define FL_P_H (FBM * PSTR)
#define FLASH_SMEM_BYTES ((FL_Q_H + FL_K_H + FL_V_H + FL_P_H) * 2)

__global__ void __launch_bounds__(256)
flash_h_kernel(const __half* __restrict__ Qe, const __half* __restrict__ Ke,
               const __half* __restrict__ Vt, __half* __restrict__ Y)
{
    extern __shared__ __half smh[];
    __half* Ps = smh + FL_Q_H + FL_K_H + FL_V_H;

    const int qt = blockIdx.x;
    const int h  = blockIdx.y;
    const int b  = blockIdx.z;
    const int q0 = qt * FBM;

    const int tid    = threadIdx.x;
    const int wid    = tid >> 5;
    const int lane   = tid & 31;
    const int g      = lane >> 2;
    const int t      = lane & 3;
    const int lane15 = lane & 15;
    const int lanehi = (lane >> 4) * 8;
    const int r0     = wid * 16;

    const __half* qbase = Qe + (((size_t)(b * NH + h)) * SEQ + q0) * DQK;
    const __half* kbase = Ke + (((size_t)(b * NH + h)) * SEQ) * DQK;
    const __half* vbase = Vt + ((size_t)(b * NKV + (h >> 1)) * HD) * SEQ;

    const uint32_t smb  = (uint32_t)__cvta_generic_to_shared(smh);
    const uint32_t qs_b = smb;
    const uint32_t ks_b = smb + FL_Q_H * 2u;
    const uint32_t vs_b = smb + (FL_Q_H + FL_K_H) * 2u;
    const uint32_t ps_b = smb + (FL_Q_H + FL_K_H + FL_V_H) * 2u;

    const uint32_t q_off = (uint32_t)((r0 + lane15) * QSTR + lanehi);
    const uint32_t k_off = (uint32_t)(lane15 * KSTR + lanehi);
    const uint32_t v_off = (uint32_t)(lane15 * VSTR + lanehi);
    const uint32_t p_off = (uint32_t)((r0 + lane15) * PSTR + lanehi);

    // Q tile 128x256 halves = 4096 chunks, 16 iters of 256 threads
    {
        #pragma unroll
        for (int l = 0; l < 16; l++) {
            int i = l * 256 + tid;
            int r  = i >> 5;              // 0..127
            int c8 = (i & 31) * 8;
            const __half* src = qbase + (size_t)r * DQK + c8;
            asm volatile("cp.async.cg.shared.global [%0], [%1], 16;\n"
                         :: "r"(qs_b + (unsigned)(r * QSTR + c8) * 2u), "l"(src));
        }
        asm volatile("cp.async.commit_group;\n");
    }

    auto issue_kv = [&](int s, int kt) {
        const int k0 = kt * FBN;
        unsigned ks = ks_b + (unsigned)s * (FBN * KSTR * 2u);
        unsigned vs = vs_b + (unsigned)s * (HD * VSTR * 2u);
        #pragma unroll
        for (int l = 0; l < 8; l++) {       // K: 64x256 halves = 2048 chunks
            int i = l * 256 + tid;
            int r  = i >> 5;                // 0..63
            int c8 = (i & 31) * 8;
            const __half* src = kbase + (size_t)(k0 + r) * DQK + c8;
            asm volatile("cp.async.cg.shared.global [%0], [%1], 16;\n"
                         :: "r"(ks + (unsigned)(r * KSTR + c8) * 2u), "l"(src));
        }
        #pragma unroll
        for (int l = 0; l < 4; l++) {       // V: 128 d x 64 t halves = 1024 chunks
            int i = l * 256 + tid;
            int rd = i >> 3;                // 0..127
            int c8 = (i & 7) * 8;           // 0..56
            const __half* src = vbase + (size_t)rd * SEQ + k0 + c8;
            asm volatile("cp.async.cg.shared.global [%0], [%1], 16;\n"
                         :: "r"(vs + (unsigned)(rd * VSTR + c8) * 2u), "l"(src));
        }
        asm volatile("cp.async.commit_group;\n");
    };

    float m[2]    = { -3.0e38f, -3.0e38f };
    float lsum[2] = { 0.0f, 0.0f };
    float oacc[16][4];
    #pragma unroll
    for (int j = 0; j < 16; j++)
        #pragma unroll
        for (int u = 0; u < 4; u++) oacc[j][u] = 0.0f;

    const float scale = 0.08838834764831845f;
    const int ntl = 2 * qt + 2;

    issue_kv(0, 0);

    for (int kt = 0; kt < ntl; kt++) {
        const int k0 = kt * FBN;
        if (kt + 1 < ntl)
            issue_kv((kt + 1) & 1, kt + 1);
        else
            asm volatile("cp.async.commit_group;\n");
        asm volatile("cp.async.wait_group 1;\n");
        __syncthreads();

        const uint32_t ksb = ks_b + (uint32_t)(kt & 1) * (FBN * KSTR * 2u);
        const uint32_t vsb = vs_b + (uint32_t)(kt & 1) * (HD * VSTR * 2u);

        // ---- S = Q K^T (16x64 per warp, k=256) ----
        float sacc[8][4];
        #pragma unroll
        for (int j = 0; j < 8; j++)
            #pragma unroll
            for (int u = 0; u < 4; u++) sacc[j][u] = 0.0f;

        #pragma unroll
        for (int ks = 0; ks < 16; ks++) {
            const int kk = ks * 16;
            uint32_t a[4];
            LDSM_X4(a[0], a[1], a[2], a[3], qs_b + (q_off + kk) * 2u);
            uint32_t bf[8][2];
            #pragma unroll
            for (int p = 0; p < 4; p++) {
                uint32_t r0r, r1r, r2r, r3r;
                LDSM_X4(r0r, r1r, r2r, r3r,
                        ksb + (k_off + p * 16 * KSTR + kk) * 2u);
                bf[2 * p][0]     = r0r;
                bf[2 * p + 1][0] = r1r;
                bf[2 * p][1]     = r2r;
                bf[2 * p + 1][1] = r3r;
            }
            #pragma unroll
            for (int j = 0; j < 8; j++)
                MMA_F16(sacc[j], a, bf[j]);
        }

        // ---- online softmax (rows r0+g, r0+g+8; warp-local) ----
        const bool diag = (kt >= 2 * qt);
        #pragma unroll
        for (int half = 0; half < 2; half++) {
            const int row = q0 + r0 + g + 8 * half;
            float v[16];
            float mloc = -3.0e38f;
            #pragma unroll
            for (int j = 0; j < 8; j++) {
                #pragma unroll
                for (int c = 0; c < 2; c++) {
                    int col = k0 + 8 * j + 2 * t + c;
                    float sv = sacc[j][2 * half + c] * scale;
                    if (diag && col > row) sv = -3.0e38f;
                    v[2 * j + c] = sv;
                    mloc = fmaxf(mloc, sv);
                }
            }
            mloc = fmaxf(mloc, __shfl_xor_sync(0xffffffffu, mloc, 1));
            mloc = fmaxf(mloc, __shfl_xor_sync(0xffffffffu, mloc, 2));
            float mn = fmaxf(m[half], mloc);
            float alpha = __expf(m[half] - mn);
            float rs = 0.0f;
            __half2 ph[8];
            #pragma unroll
            for (int j = 0; j < 8; j++) {
                float p0 = __expf(v[2 * j]     - mn);
                float p1 = __expf(v[2 * j + 1] - mn);
                __half2 h2 = __floats2half2_rn(p0, p1);
                ph[j] = h2;
                float2 pr = __half22float2(h2);
                rs += pr.x + pr.y;
            }
            rs += __shfl_xor_sync(0xffffffffu, rs, 1);
            rs += __shfl_xor_sync(0xffffffffu, rs, 2);
            lsum[half] = lsum[half] * alpha + rs;
            m[half] = mn;
            #pragma unroll
            for (int j = 0; j < 16; j++) {
                oacc[j][2 * half]     *= alpha;
                oacc[j][2 * half + 1] *= alpha;
            }
            #pragma unroll
            for (int j = 0; j < 8; j++)
                *(__half2*)(Ps + (size_t)(r0 + g + 8 * half) * PSTR
                            + 8 * j + 2 * t) = ph[j];
        }
        __syncwarp();

        // ---- O += P V (16x128 per warp, k=64) ----
        #pragma unroll
        for (int ks = 0; ks < 4; ks++) {
            const int kk = ks * 16;
            uint32_t a[4];
            LDSM_X4(a[0], a[1], a[2], a[3], ps_b + (p_off + kk) * 2u);
            #pragma unroll
            for (int p = 0; p < 8; p++) {
                uint32_t r0r, r1r, r2r, r3r;
                LDSM_X4(r0r, r1r, r2r, r3r,
                        vsb + (v_off + p * 16 * VSTR + kk) * 2u);
                uint32_t b0[2] = { r0r, r2r };
                uint32_t b1[2] = { r1r, r3r };
                MMA_F16(oacc[2 * p],     a, b0);
                MMA_F16(oacc[2 * p + 1], a, b1);
            }
        }
        __syncthreads();
    }

    // epilogue
    #pragma unroll
    for (int half = 0; half < 2; half++) {
        const int row = q0 + r0 + g + 8 * half;
        const float inv = 1.0f / lsum[half];
        __half* yr = Y + ((size_t)b * SEQ + row) * DM + h * HD;
        #pragma unroll
        for (int j = 0; j < 16; j++)
            *(__half2*)(yr + 8 * j + 2 * t) =
                __floats2half2_rn(oacc[j][2 * half] * inv,
                                  oacc[j][2 * half + 1] * inv);
    }
}

// ---------------------------------------------------------------------------
// Launch
// ---------------------------------------------------------------------------
extern "C" void kernel_launch(void* const* d_in, const int* in_sizes, int n_in,
                              void* d_out, int out_size)
{
    const float* x     = (const float*)d_in[0];
    const float* Wq    = (const float*)d_in[1];
    const float* Wk    = (const float*)d_in[2];
    const float* Wv    = (const float*)d_in[3];
    const float* Wo    = (const float*)d_in[4];
    const float* delta = (const float*)d_in[5];
    float* out = (float*)d_out;

    float  *q_, *k_, *v_, *cs_, *sn_, *cd_, *sd_;
    __half *qe_, *ke_, *vt_, *yh_, *xh_, *wq_, *wk_, *wv_, *wo_;
    cudaGetSymbolAddress((void**)&q_,  g_q);
    cudaGetSymbolAddress((void**)&k_,  g_k);
    cudaGetSymbolAddress((void**)&v_,  g_v);
    cudaGetSymbolAddress((void**)&qe_, g_qe);
    cudaGetSymbolAddress((void**)&ke_, g_ke);
    cudaGetSymbolAddress((void**)&vt_, g_vt);
    cudaGetSymbolAddress((void**)&yh_, g_yh);
    cudaGetSymbolAddress((void**)&xh_, g_xh);
    cudaGetSymbolAddress((void**)&wq_, g_wq);
    cudaGetSymbolAddress((void**)&wk_, g_wk);
    cudaGetSymbolAddress((void**)&wv_, g_wv);
    cudaGetSymbolAddress((void**)&wo_, g_wo);
    cudaGetSymbolAddress((void**)&cs_, g_cs);
    cudaGetSymbolAddress((void**)&sn_, g_sn);
    cudaGetSymbolAddress((void**)&cd_, g_cd);
    cudaGetSymbolAddress((void**)&sd_, g_sd);

    const int M = BSZ * SEQ;   // 4096

    cudaFuncSetAttribute(gemm_h_kernel,
                         cudaFuncAttributeMaxDynamicSharedMemorySize,
                         GEMM_SMEM_BYTES);
    cudaFuncSetAttribute(flash_h_kernel,
                         cudaFuncAttributeMaxDynamicSharedMemorySize,
                         FLASH_SMEM_BYTES);

    // prep
    {
        int n = BSZ * SEQ * DM;
        f2h_kernel<<<(n / 4 + 255) / 256, 256>>>(x, xh_, n);
        dim3 blk(32, 8);
        transpose_h_kernel<<<dim3(DM / 32,       DM / 32), blk>>>(Wq, wq_, DM, DM);
        transpose_h_kernel<<<dim3(NKV * HD / 32, DM / 32), blk>>>(Wk, wk_, DM, NKV * HD);
        transpose_h_kernel<<<dim3(NKV * HD / 32, DM / 32), blk>>>(Wv, wv_, DM, NKV * HD);
        transpose_h_kernel<<<dim3(DM / 32,       DM / 32), blk>>>(Wo, wo_, DM, DM);
        angles_kernel<<<(SEQ * HD + 255) / 256, 256>>>(cs_, sn_);
        delta_kernel<<<(NH * HD + 255) / 256, 256>>>(delta, cd_, sd_);
    }

    // projections
    gemm_h_kernel<<<dim3(DM / 128, M / 128, 1), 128, GEMM_SMEM_BYTES>>>(
        xh_, wq_, q_, wq_, q_, M, DM, DM);
    gemm_h_kernel<<<dim3(NKV * HD / 128, M / 128, 2), 128, GEMM_SMEM_BYTES>>>(
        xh_, wk_, k_, wv_, v_, M, NKV * HD, DM);

    // encode + V transpose
    {
        const int total = BSZ * NH * SEQ * HD;
        encode_kernel<<<(total + 255) / 256, 256>>>(q_, k_, cs_, sn_, cd_, sd_,
                                                    qe_, ke_);
        vtrans_kernel<<<dim3(SEQ / 32, HD / 32, BSZ * NKV), dim3(32, 8)>>>(v_, vt_);
    }

    // flash attention
    flash_h_kernel<<<dim3(SEQ / FBM, NH, BSZ), 256, FLASH_SMEM_BYTES>>>(
        qe_, ke_, vt_, yh_);

    // output projection
    gemm_h_kernel<<<dim3(DM / 128, M / 128, 1), 128, GEMM_SMEM_BYTES>>>(
        yh_, wo_, out, wo_, out, M, DM, DM);
}